// round 1
// baseline (speedup 1.0000x reference)
#include <cuda_runtime.h>
#include <math.h>

// ---------------- problem constants ----------------
#define BSZ    1024
#define NNODE  80
#define LMIR   30
#define NDIM   256
#define FDIM   512
#define HEADS  4
#define CDIM   128
#define OUTD   128
#define MROWS  (BSZ*NNODE)       // 81920
#define LN_EPS 1e-5f

// ---------------- device scratch (no allocations allowed) ----------------
__device__ float g_x0  [(size_t)MROWS*NDIM];   // concat(enc)+node_type_emb
__device__ float g_x   [(size_t)MROWS*FDIM];   // node features
__device__ float g_xl  [(size_t)MROWS*FDIM];
__device__ float g_xr  [(size_t)MROWS*FDIM];
__device__ float g_h   [(size_t)MROWS*FDIM];   // GAT out / GEMM temp
__device__ float g_pool[(size_t)BSZ*2*FDIM];   // [mean | max]
__device__ float g_o   [(size_t)BSZ*OUTD];     // pre-LN head output

// ---------------- build x0 = concat(mirna+emb0, target+emb1) ----------------
__global__ void build_x0(const float* __restrict__ mirna,
                         const float* __restrict__ target,
                         const float* __restrict__ ntype) {
    int i4 = blockIdx.x * blockDim.x + threadIdx.x;      // over MROWS * 64
    if (i4 >= MROWS * (NDIM / 4)) return;
    int row = i4 >> 6;
    int c4  = (i4 & 63) << 2;
    int b = row / NNODE, v = row % NNODE;
    const float* src;
    const float* emb;
    if (v < LMIR) { src = mirna  + ((size_t)b*LMIR + v) * NDIM;        emb = ntype; }
    else          { src = target + ((size_t)b*(NNODE-LMIR) + (v-LMIR)) * NDIM; emb = ntype + NDIM; }
    float4 a = *(const float4*)(src + c4);
    float4 e = *(const float4*)(emb + c4);
    float4 o = make_float4(a.x+e.x, a.y+e.y, a.z+e.z, a.w+e.w);
    *(float4*)(g_x0 + (size_t)row*NDIM + c4) = o;
}

// ---------------- classic fp32 SGEMM: C = A[MxK] * B[KxN] + bias ----------------
// BM=BN=128, BK=8, 256 threads, 8x8 per thread. All dims multiples of tile.
__global__ __launch_bounds__(256) void sgemm128(
    const float* __restrict__ A, const float* __restrict__ B,
    const float* __restrict__ bias, float* __restrict__ C,
    int M, int N, int K)
{
    __shared__ float As[8][128];
    __shared__ float Bs[8][128];
    const int tid = threadIdx.x;
    const int bx = blockIdx.x, by = blockIdx.y;

    const int arow = tid >> 1, acol = (tid & 1) << 2;     // A: 128 rows x 8 cols
    const int brow = tid >> 5, bcol = (tid & 31) << 2;    // B: 8 rows x 128 cols
    const float* Ag = A + (size_t)(by*128 + arow) * K + acol;
    const float* Bg = B + (size_t)brow * N + bx*128 + bcol;

    const int trow = (tid >> 4) << 3;
    const int tcol = (tid & 15) << 3;

    float acc[8][8];
    #pragma unroll
    for (int i = 0; i < 8; i++)
        #pragma unroll
        for (int j = 0; j < 8; j++) acc[i][j] = 0.f;

    const int ntile = K >> 3;
    for (int t = 0; t < ntile; ++t) {
        float4 av = *(const float4*)Ag;
        float4 bv = *(const float4*)Bg;
        __syncthreads();
        As[acol+0][arow] = av.x;
        As[acol+1][arow] = av.y;
        As[acol+2][arow] = av.z;
        As[acol+3][arow] = av.w;
        *(float4*)&Bs[brow][bcol] = bv;
        __syncthreads();
        #pragma unroll
        for (int k = 0; k < 8; ++k) {
            float4 a0 = *(const float4*)&As[k][trow];
            float4 a1 = *(const float4*)&As[k][trow+4];
            float4 b0 = *(const float4*)&Bs[k][tcol];
            float4 b1 = *(const float4*)&Bs[k][tcol+4];
            float ar[8] = {a0.x,a0.y,a0.z,a0.w,a1.x,a1.y,a1.z,a1.w};
            float br[8] = {b0.x,b0.y,b0.z,b0.w,b1.x,b1.y,b1.z,b1.w};
            #pragma unroll
            for (int i = 0; i < 8; i++)
                #pragma unroll
                for (int j = 0; j < 8; j++)
                    acc[i][j] += ar[i] * br[j];
        }
        Ag += 8;
        Bg += (size_t)8 * N;
    }

    float4 bi0 = *(const float4*)&bias[bx*128 + tcol];
    float4 bi1 = *(const float4*)&bias[bx*128 + tcol + 4];
    #pragma unroll
    for (int i = 0; i < 8; i++) {
        float* Cp = C + (size_t)(by*128 + trow + i) * N + bx*128 + tcol;
        float4 o0 = make_float4(acc[i][0]+bi0.x, acc[i][1]+bi0.y, acc[i][2]+bi0.z, acc[i][3]+bi0.w);
        float4 o1 = make_float4(acc[i][4]+bi1.x, acc[i][5]+bi1.y, acc[i][6]+bi1.z, acc[i][7]+bi1.w);
        *(float4*)Cp       = o0;
        *(float4*)(Cp + 4) = o1;
    }
}

// ---------------- warp-per-row LayerNorm (+optional exact GELU) ----------------
// width must be a multiple of 128 (512 or 128 here).
__global__ void ln_gelu(const float* __restrict__ in, float* __restrict__ out,
                        const float* __restrict__ g, const float* __restrict__ b,
                        int rows, int width, int dogelu)
{
    int warp = (blockIdx.x * blockDim.x + threadIdx.x) >> 5;
    if (warp >= rows) return;
    int lane = threadIdx.x & 31;
    const float* rp = in + (size_t)warp * width;
    int nv = width >> 7;              // float4 per lane
    float vals[16];
    float s = 0.f, ss = 0.f;
    for (int i = 0; i < nv; i++) {
        float4 v = *(const float4*)(rp + lane*4 + i*128);
        vals[i*4+0]=v.x; vals[i*4+1]=v.y; vals[i*4+2]=v.z; vals[i*4+3]=v.w;
        s  += v.x + v.y + v.z + v.w;
        ss += v.x*v.x + v.y*v.y + v.z*v.z + v.w*v.w;
    }
    #pragma unroll
    for (int o = 16; o; o >>= 1) {
        s  += __shfl_xor_sync(0xffffffffu, s,  o);
        ss += __shfl_xor_sync(0xffffffffu, ss, o);
    }
    float inv_w = 1.f / (float)width;
    float mu = s * inv_w;
    float var = ss * inv_w - mu * mu;
    float r = rsqrtf(var + LN_EPS);
    float* op = out + (size_t)warp * width;
    for (int i = 0; i < nv; i++) {
        int f = lane*4 + i*128;
        float4 gg = *(const float4*)(g + f);
        float4 bb = *(const float4*)(b + f);
        float y0 = (vals[i*4+0]-mu)*r*gg.x + bb.x;
        float y1 = (vals[i*4+1]-mu)*r*gg.y + bb.y;
        float y2 = (vals[i*4+2]-mu)*r*gg.z + bb.z;
        float y3 = (vals[i*4+3]-mu)*r*gg.w + bb.w;
        if (dogelu) {
            y0 = 0.5f*y0*(1.f+erff(y0*0.70710678118654752f));
            y1 = 0.5f*y1*(1.f+erff(y1*0.70710678118654752f));
            y2 = 0.5f*y2*(1.f+erff(y2*0.70710678118654752f));
            y3 = 0.5f*y3*(1.f+erff(y3*0.70710678118654752f));
        }
        *(float4*)(op + f) = make_float4(y0, y1, y2, y3);
    }
}

// ---------------- residual + LayerNorm (+optional GELU), x <- LN(h+bo+x) ----------------
__global__ void resid_ln(const float* __restrict__ h, float* __restrict__ x,
                         const float* __restrict__ bo, const float* __restrict__ g,
                         const float* __restrict__ b, int dogelu)
{
    int warp = (blockIdx.x * blockDim.x + threadIdx.x) >> 5;
    if (warp >= MROWS) return;
    int lane = threadIdx.x & 31;
    const float* hp = h + (size_t)warp * FDIM;
    float* xp = x + (size_t)warp * FDIM;
    float vals[16];
    float s = 0.f, ss = 0.f;
    #pragma unroll
    for (int i = 0; i < 4; i++) {
        int f = lane*4 + i*128;
        float4 hv = *(const float4*)(hp + f);
        float4 xv = *(const float4*)(xp + f);
        float4 bv = *(const float4*)(bo + f);
        float v0 = hv.x + bv.x + xv.x;
        float v1 = hv.y + bv.y + xv.y;
        float v2 = hv.z + bv.z + xv.z;
        float v3 = hv.w + bv.w + xv.w;
        vals[i*4+0]=v0; vals[i*4+1]=v1; vals[i*4+2]=v2; vals[i*4+3]=v3;
        s  += v0+v1+v2+v3;
        ss += v0*v0+v1*v1+v2*v2+v3*v3;
    }
    #pragma unroll
    for (int o = 16; o; o >>= 1) {
        s  += __shfl_xor_sync(0xffffffffu, s,  o);
        ss += __shfl_xor_sync(0xffffffffu, ss, o);
    }
    float mu = s * (1.f/FDIM);
    float var = ss * (1.f/FDIM) - mu*mu;
    float r = rsqrtf(var + LN_EPS);
    #pragma unroll
    for (int i = 0; i < 4; i++) {
        int f = lane*4 + i*128;
        float4 gg = *(const float4*)(g + f);
        float4 bb = *(const float4*)(b + f);
        float y0 = (vals[i*4+0]-mu)*r*gg.x + bb.x;
        float y1 = (vals[i*4+1]-mu)*r*gg.y + bb.y;
        float y2 = (vals[i*4+2]-mu)*r*gg.z + bb.z;
        float y3 = (vals[i*4+3]-mu)*r*gg.w + bb.w;
        if (dogelu) {
            y0 = 0.5f*y0*(1.f+erff(y0*0.70710678118654752f));
            y1 = 0.5f*y1*(1.f+erff(y1*0.70710678118654752f));
            y2 = 0.5f*y2*(1.f+erff(y2*0.70710678118654752f));
            y3 = 0.5f*y3*(1.f+erff(y3*0.70710678118654752f));
        }
        *(float4*)(xp + f) = make_float4(y0, y1, y2, y3);
    }
}

// ---------------- GAT aggregation (analytic static graph, <=5 in-edges/node) ----------------
// block = one batch element, 256 threads; xl tile in dyn SMEM; warp per (node,head).
__global__ __launch_bounds__(256) void gat(
    const float* __restrict__ xl, const float* __restrict__ xr,
    const float* __restrict__ etype_emb,   // [3,4]
    const float* __restrict__ We,          // [4,512] (this layer)
    const float* __restrict__ att,         // [4,128] (this layer)
    float* __restrict__ hout)
{
    extern __shared__ float sm[];
    float* xls = sm;                       // 80*512
    float* ee0 = sm + NNODE*FDIM;          // 512
    float* ee2 = ee0 + FDIM;               // 512
    const int b = blockIdx.x;
    const int tid = threadIdx.x;

    for (int f = tid; f < FDIM; f += 256) {
        float s0 = 0.f, s2 = 0.f;
        #pragma unroll
        for (int j = 0; j < 4; j++) {
            float w = We[j*FDIM + f];
            s0 += etype_emb[j]     * w;   // type 0
            s2 += etype_emb[8 + j] * w;   // type 2
        }
        ee0[f] = s0; ee2[f] = s2;
    }
    const float* xlb = xl + (size_t)b * NNODE * FDIM;
    for (int i4 = tid; i4 < NNODE*FDIM/4; i4 += 256)
        *(float4*)(xls + (size_t)i4*4) = *(const float4*)(xlb + (size_t)i4*4);
    __syncthreads();

    const int lane = tid & 31, wid = tid >> 5;
    for (int t = wid; t < NNODE*HEADS; t += 8) {
        const int v = t >> 2, h = t & 3;
        const int base = h*CDIM + lane;                       // +32*j
        const float* xrp = xr + ((size_t)b*NNODE + v)*FDIM + base;
        float xrr[4], atr[4];
        #pragma unroll
        for (int j = 0; j < 4; j++) {
            xrr[j] = xrp[32*j];
            atr[j] = att[h*CDIM + lane + 32*j];
        }
        const int lo = (v < LMIR) ? 0 : LMIR;
        const int hi = (v < LMIR) ? (LMIR-1) : (NNODE-1);
        // 5 fixed edge slots: v-1, v+1 (type0); v-2, v+2 (type2); self
        int   srcs[5];
        float c0[5], c2[5], valid[5];
        srcs[0]=v-1; srcs[1]=v+1; srcs[2]=v-2; srcs[3]=v+2; srcs[4]=v;
        valid[0] = (v-1 >= lo) ? 1.f : 0.f;
        valid[1] = (v+1 <= hi) ? 1.f : 0.f;
        valid[2] = (v-2 >= lo) ? 1.f : 0.f;
        valid[3] = (v+2 <= hi) ? 1.f : 0.f;
        valid[4] = 1.f;
        c0[0]=1.f; c2[0]=0.f;  c0[1]=1.f; c2[1]=0.f;
        c0[2]=0.f; c2[2]=1.f;  c0[3]=0.f; c2[3]=1.f;
        float n0 = valid[0] + valid[1];
        float n2 = valid[2] + valid[3];
        float inv = 1.f / (n0 + n2);
        c0[4] = n0 * inv; c2[4] = n2 * inv;
        #pragma unroll
        for (int e = 0; e < 5; e++) {                 // clamp srcs for safe smem read
            int s = srcs[e];
            s = s < 0 ? 0 : (s > NNODE-1 ? NNODE-1 : s);
            srcs[e] = s;
        }

        float a[5];
        #pragma unroll
        for (int e = 0; e < 5; e++) {
            const float* xp = xls + srcs[e]*FDIM + base;
            float p = 0.f;
            #pragma unroll
            for (int j = 0; j < 4; j++) {
                int off = 32*j;
                float m = xp[off] + xrr[j] + c0[e]*ee0[base+off] + c2[e]*ee2[base+off];
                m = (m > 0.f) ? m : 0.2f*m;           // leaky_relu(0.2)
                p += m * atr[j];
            }
            #pragma unroll
            for (int o = 16; o; o >>= 1) p += __shfl_xor_sync(0xffffffffu, p, o);
            a[e] = (valid[e] > 0.f) ? p : -1e30f;
        }
        float amax = a[0];
        #pragma unroll
        for (int e = 1; e < 5; e++) amax = fmaxf(amax, a[e]);
        float den = 0.f;
        #pragma unroll
        for (int e = 0; e < 5; e++) { a[e] = expf(a[e] - amax); den += a[e]; }
        float invd = 1.f / den;

        float o0=0.f, o1=0.f, o2=0.f, o3=0.f;
        #pragma unroll
        for (int e = 0; e < 5; e++) {
            float al = a[e] * invd;
            const float* xp = xls + srcs[e]*FDIM + base;
            o0 += al * xp[0];
            o1 += al * xp[32];
            o2 += al * xp[64];
            o3 += al * xp[96];
        }
        float* op = hout + ((size_t)b*NNODE + v)*FDIM + base;
        op[0]=o0; op[32]=o1; op[64]=o2; op[96]=o3;
    }
}

// ---------------- mean/max pool over nodes ----------------
__global__ void pool(const float* __restrict__ x, float* __restrict__ pooled) {
    int b = blockIdx.x;
    int f = threadIdx.x;                  // 512 threads
    const float* xp = x + (size_t)b * NNODE * FDIM + f;
    float s = 0.f, mx = -3.4e38f;
    #pragma unroll 4
    for (int v = 0; v < NNODE; v++) {
        float val = xp[(size_t)v * FDIM];
        s += val;
        mx = fmaxf(mx, val);
    }
    pooled[(size_t)b*2*FDIM + f]        = s * (1.f/NNODE);
    pooled[(size_t)b*2*FDIM + FDIM + f] = mx;
}

// ---------------- head GEMM: [1024,1024] @ [1024,128] + bias ----------------
__global__ __launch_bounds__(128) void gemm_out(
    const float* __restrict__ A, const float* __restrict__ Bw,
    const float* __restrict__ bias, float* __restrict__ C)
{
    __shared__ float As[8][1024];
    const int r0 = blockIdx.x * 8;
    const int tid = threadIdx.x;
    for (int i4 = tid; i4 < 8*1024/4; i4 += 128)
        *(float4*)(&As[0][0] + (size_t)i4*4) = *(const float4*)(A + (size_t)r0*1024 + (size_t)i4*4);
    __syncthreads();
    float acc[8];
    #pragma unroll
    for (int r = 0; r < 8; r++) acc[r] = 0.f;
    #pragma unroll 4
    for (int k = 0; k < 1024; k++) {
        float bv = Bw[(size_t)k*128 + tid];
        #pragma unroll
        for (int r = 0; r < 8; r++) acc[r] += As[r][k] * bv;
    }
    float bi = bias[tid];
    #pragma unroll
    for (int r = 0; r < 8; r++)
        C[(size_t)(r0 + r)*128 + tid] = acc[r] + bi;
}

// ---------------- launch ----------------
extern "C" void kernel_launch(void* const* d_in, const int* in_sizes, int n_in,
                              void* d_out, int out_size) {
    const float* mirna  = (const float*)d_in[0];
    const float* target = (const float*)d_in[1];
    const float* ntype  = (const float*)d_in[2];
    const float* etype  = (const float*)d_in[3];
    const float* in_W   = (const float*)d_in[4];
    const float* in_b   = (const float*)d_in[5];
    const float* in_lng = (const float*)d_in[6];
    const float* in_lnb = (const float*)d_in[7];
    const float* Wl     = (const float*)d_in[8];
    const float* bl     = (const float*)d_in[9];
    const float* Wr     = (const float*)d_in[10];
    const float* br     = (const float*)d_in[11];
    const float* We     = (const float*)d_in[12];
    const float* attw   = (const float*)d_in[13];
    const float* bo     = (const float*)d_in[14];
    const float* lng    = (const float*)d_in[15];
    const float* lnb    = (const float*)d_in[16];
    const float* outW   = (const float*)d_in[17];
    const float* outb   = (const float*)d_in[18];
    const float* olng   = (const float*)d_in[19];
    const float* olnb   = (const float*)d_in[20];
    float* out = (float*)d_out;

    float *x0p, *xp, *xlp, *xrp, *hp, *poolp, *op;
    cudaGetSymbolAddress((void**)&x0p,   g_x0);
    cudaGetSymbolAddress((void**)&xp,    g_x);
    cudaGetSymbolAddress((void**)&xlp,   g_xl);
    cudaGetSymbolAddress((void**)&xrp,   g_xr);
    cudaGetSymbolAddress((void**)&hp,    g_h);
    cudaGetSymbolAddress((void**)&poolp, g_pool);
    cudaGetSymbolAddress((void**)&op,    g_o);

    const int GAT_SMEM = (NNODE*FDIM + 2*FDIM) * sizeof(float);   // 167936
    cudaFuncSetAttribute(gat, cudaFuncAttributeMaxDynamicSharedMemorySize, GAT_SMEM);

    // 1. build x0
    build_x0<<<(MROWS*64 + 255)/256, 256>>>(mirna, target, ntype);

    // 2. input projection -> g_h, then LN+GELU -> g_x
    dim3 gproj(FDIM/128, MROWS/128);
    sgemm128<<<gproj, 256>>>(x0p, in_W, in_b, hp, MROWS, FDIM, NDIM);
    ln_gelu<<<(MROWS*32 + 255)/256, 256>>>(hp, xp, in_lng, in_lnb, MROWS, FDIM, 1);

    // 3. GAT layers
    for (int i = 0; i < 2; i++) {
        sgemm128<<<gproj, 256>>>(xp, Wl + (size_t)i*FDIM*FDIM, bl + (size_t)i*FDIM, xlp, MROWS, FDIM, FDIM);
        sgemm128<<<gproj, 256>>>(xp, Wr + (size_t)i*FDIM*FDIM, br + (size_t)i*FDIM, xrp, MROWS, FDIM, FDIM);
        gat<<<BSZ, 256, GAT_SMEM>>>(xlp, xrp, etype,
                                    We + (size_t)i*HEADS*FDIM,
                                    attw + (size_t)i*HEADS*CDIM, hp);
        resid_ln<<<(MROWS*32 + 255)/256, 256>>>(hp, xp, bo + (size_t)i*FDIM,
                                                lng + (size_t)i*FDIM, lnb + (size_t)i*FDIM,
                                                (i == 0) ? 1 : 0);
    }

    // 4. pool + head
    pool<<<BSZ, FDIM>>>(xp, poolp);
    gemm_out<<<BSZ/8, 128>>>(poolp, outW, outb, op);
    ln_gelu<<<(BSZ*32 + 255)/256, 256>>>(op, out, olng, olnb, BSZ, OUTD, 1);
}

// round 4
// speedup vs baseline: 1.9142x; 1.9142x over previous
#include <cuda_runtime.h>
#include <cuda_bf16.h>
#include <math.h>
#include <stdint.h>

// ---------------- problem constants ----------------
#define BSZ    1024
#define NNODE  80
#define LMIR   30
#define NDIM   256
#define FDIM   512
#define HEADS  4
#define CDIM   128
#define OUTD   128
#define MROWS  (BSZ*NNODE)       // 81920
#define LN_EPS 1e-5f

// GEMM tiling (mma.sync path, sm_100 baseline — no tcgen05 on this toolchain target)
#define BM 128
#define BN 128
#define BKK 32
#define NSTG 3
#define STG_BYTES (4*128*64)            // Ah,Al,Bh,Bl tiles: 4 * 8KB = 32KB
#define GEMM_SMEM (NSTG*STG_BYTES)      // 96KB

// ---------------- device scratch ----------------
__device__ __nv_bfloat16 g_x0h [(size_t)MROWS*NDIM];
__device__ __nv_bfloat16 g_x0l [(size_t)MROWS*NDIM];
__device__ __nv_bfloat16 g_wih [(size_t)FDIM*NDIM];        // in_W^T [N=512, K=256]
__device__ __nv_bfloat16 g_wil [(size_t)FDIM*NDIM];
__device__ __nv_bfloat16 g_wch [(size_t)2*1024*FDIM];      // concat(Wl,Wr)^T per layer [N=1024,K=512]
__device__ __nv_bfloat16 g_wcl [(size_t)2*1024*FDIM];
__device__ float         g_bcat[(size_t)2*1024];
__device__ float         g_x   [(size_t)MROWS*FDIM];       // node features fp32
__device__ __nv_bfloat16 g_xh  [(size_t)MROWS*FDIM];       // x hi
__device__ __nv_bfloat16 g_xlo [(size_t)MROWS*FDIM];       // x lo
__device__ float         g_xlr [(size_t)MROWS*1024];       // [xl | xr] per layer
__device__ float         g_h   [(size_t)MROWS*FDIM];       // GEMM1 out / GAT out
__device__ float         g_pool[(size_t)BSZ*2*FDIM];
__device__ float         g_o   [(size_t)BSZ*OUTD];

// ---------------- PTX helpers (all sm_80/90 baseline; NO tcgen05) ----------------
__device__ __forceinline__ uint32_t smem_u32(const void* p) {
    uint32_t a;
    asm("{ .reg .u64 t; cvta.to.shared.u64 t, %1; cvt.u32.u64 %0, t; }" : "=r"(a) : "l"(p));
    return a;
}
__device__ __forceinline__ void cp16(uint32_t saddr, const void* gaddr) {
    asm volatile("cp.async.cg.shared.global [%0], [%1], 16;" :: "r"(saddr), "l"(gaddr));
}
#define CP_COMMIT() asm volatile("cp.async.commit_group;" ::: "memory")

// SW64 swizzle: bits[5:4] ^= bits[8:7]  (conflict-free ldmatrix on 64B rows)
__device__ __forceinline__ uint32_t swz64(uint32_t off) { return off ^ ((off >> 3) & 0x30); }

#define LDMX4(r0,r1,r2,r3,a) \
    asm volatile("ldmatrix.sync.aligned.m8n8.x4.shared.b16 {%0,%1,%2,%3}, [%4];" \
        : "=r"(r0), "=r"(r1), "=r"(r2), "=r"(r3) : "r"(a))

#define MMA16816(c, a, b0, b1) \
    asm volatile("mma.sync.aligned.m16n8k16.row.col.f32.bf16.bf16.f32 " \
        "{%0,%1,%2,%3}, {%4,%5,%6,%7}, {%8,%9}, {%0,%1,%2,%3};" \
        : "+f"((c)[0]), "+f"((c)[1]), "+f"((c)[2]), "+f"((c)[3]) \
        : "r"((a)[0]), "r"((a)[1]), "r"((a)[2]), "r"((a)[3]), "r"(b0), "r"(b1))

// ---------------- bf16 split helpers ----------------
__device__ __forceinline__ void split_store4(__nv_bfloat16* hi, __nv_bfloat16* lo, size_t off,
                                             float a, float b, float c, float d) {
    __nv_bfloat16 h0 = __float2bfloat16_rn(a), h1 = __float2bfloat16_rn(b);
    __nv_bfloat16 h2 = __float2bfloat16_rn(c), h3 = __float2bfloat16_rn(d);
    __nv_bfloat16 l0 = __float2bfloat16_rn(a - __bfloat162float(h0));
    __nv_bfloat16 l1 = __float2bfloat16_rn(b - __bfloat162float(h1));
    __nv_bfloat16 l2 = __float2bfloat16_rn(c - __bfloat162float(h2));
    __nv_bfloat16 l3 = __float2bfloat16_rn(d - __bfloat162float(h3));
    ushort4 hv, lv;
    hv.x = *(unsigned short*)&h0; hv.y = *(unsigned short*)&h1; hv.z = *(unsigned short*)&h2; hv.w = *(unsigned short*)&h3;
    lv.x = *(unsigned short*)&l0; lv.y = *(unsigned short*)&l1; lv.z = *(unsigned short*)&l2; lv.w = *(unsigned short*)&l3;
    *(ushort4*)(hi + off) = hv;
    *(ushort4*)(lo + off) = lv;
}

// ---------------- weight prep: transpose + split ----------------
__global__ void prep_weights(const float* __restrict__ in_W,
                             const float* __restrict__ Wl, const float* __restrict__ Wr,
                             const float* __restrict__ bl, const float* __restrict__ br) {
    const int T0 = FDIM * NDIM;            // 131072
    const int T1 = 2 * 1024 * FDIM;        // 1048576
    int t = blockIdx.x * blockDim.x + threadIdx.x;
    if (t < T0) {
        int n = t / NDIM, k = t % NDIM;
        float v = in_W[(size_t)k * FDIM + n];
        __nv_bfloat16 h = __float2bfloat16_rn(v);
        g_wih[t] = h;
        g_wil[t] = __float2bfloat16_rn(v - __bfloat162float(h));
        return;
    }
    t -= T0;
    if (t < T1) {
        int i = t / (1024 * FDIM);
        int r = t % (1024 * FDIM);
        int n = r / FDIM, k = r % FDIM;
        float v = (n < FDIM) ? Wl[(size_t)i*FDIM*FDIM + (size_t)k*FDIM + n]
                             : Wr[(size_t)i*FDIM*FDIM + (size_t)k*FDIM + (n - FDIM)];
        __nv_bfloat16 h = __float2bfloat16_rn(v);
        g_wch[t] = h;
        g_wcl[t] = __float2bfloat16_rn(v - __bfloat162float(h));
        return;
    }
    t -= T1;
    if (t < 2 * 1024) {
        int i = t / 1024, n = t % 1024;
        g_bcat[t] = (n < FDIM) ? bl[i*FDIM + n] : br[i*FDIM + (n - FDIM)];
    }
}

// ---------------- build x0 (hi/lo bf16 directly) ----------------
__global__ void build_x0(const float* __restrict__ mirna,
                         const float* __restrict__ target,
                         const float* __restrict__ ntype) {
    int i4 = blockIdx.x * blockDim.x + threadIdx.x;
    if (i4 >= MROWS * (NDIM / 4)) return;
    int row = i4 >> 6;
    int c4  = (i4 & 63) << 2;
    int b = row / NNODE, v = row % NNODE;
    const float* src; const float* emb;
    if (v < LMIR) { src = mirna  + ((size_t)b*LMIR + v) * NDIM;                emb = ntype; }
    else          { src = target + ((size_t)b*(NNODE-LMIR) + (v-LMIR)) * NDIM; emb = ntype + NDIM; }
    float4 a = *(const float4*)(src + c4);
    float4 e = *(const float4*)(emb + c4);
    split_store4(g_x0h, g_x0l, (size_t)row*NDIM + c4, a.x+e.x, a.y+e.y, a.z+e.z, a.w+e.w);
}

// ---------------- bf16 3-term split GEMM via mma.sync ----------------
// D[M,N] = A[M,K] @ B^T + bias;  A row-major [M,K], B row-major [N,K] (= col-major operand).
// grid (N/128, M/128), 256 threads = 8 warps (4 x 2), warp tile 32x64.
__global__ __launch_bounds__(256) void gemm_bf16(
    const __nv_bfloat16* __restrict__ Ah, const __nv_bfloat16* __restrict__ Al,
    const __nv_bfloat16* __restrict__ Bh, const __nv_bfloat16* __restrict__ Bl,
    const float* __restrict__ bias, float* __restrict__ C, int K)
{
    extern __shared__ char sm[];
    const uint32_t smem_base = smem_u32(sm);
    const int tid = threadIdx.x;
    const int wid = tid >> 5, lane = tid & 31;
    const int m0 = blockIdx.y * BM;
    const int n0 = blockIdx.x * BN;
    const int ldC = gridDim.x * BN;
    const int nchunk = K >> 5;              // K per stage = 32
    const int warpM = (wid & 3) * 32;
    const int warpN = (wid >> 2) * 64;
    const int lrow = lane & 7, midx = lane >> 3;

    float acc[2][8][4];
    #pragma unroll
    for (int i = 0; i < 2; i++)
        #pragma unroll
        for (int j = 0; j < 8; j++)
            #pragma unroll
            for (int q = 0; q < 4; q++) acc[i][j][q] = 0.f;

    const __nv_bfloat16* bases[4] = { Ah + (size_t)m0 * K, Al + (size_t)m0 * K,
                                      Bh + (size_t)n0 * K, Bl + (size_t)n0 * K };

    auto load_stage = [&](int slot, int c) {
        const uint32_t sb = smem_base + slot * STG_BYTES;
        const int k0 = c * BKK;
        #pragma unroll
        for (int i = 0; i < 8; i++) {
            int idx = tid + i * 256;              // 0..2047
            int sub = idx >> 9;                   // 0:Ah 1:Al 2:Bh 3:Bl
            int w   = idx & 511;
            int row = w >> 2, ch = w & 3;         // 128 rows x 4 16B-chunks
            uint32_t so = sb + (sub << 13) + swz64((row << 6) + (ch << 4));
            cp16(so, bases[sub] + (size_t)row * K + k0 + ch * 8);
        }
        CP_COMMIT();
    };

    load_stage(0, 0);
    load_stage(1, 1);

    for (int c = 0; c < nchunk; ++c) {
        if (c < nchunk - 1) asm volatile("cp.async.wait_group 1;" ::: "memory");
        else                asm volatile("cp.async.wait_group 0;" ::: "memory");
        __syncthreads();
        if (c + 2 < nchunk) load_stage((c + 2) % NSTG, c + 2);

        const uint32_t sb = smem_base + (c % NSTG) * STG_BYTES;
        #pragma unroll
        for (int kc = 0; kc < 2; ++kc) {          // two k16 steps per stage
            uint32_t ah[2][4], alr[2][4], bh[4][4], blr[4][4];
            // A fragments: x4 = (m0k0, m1k0, m0k1, m1k1) of a 16x16 tile
            #pragma unroll
            for (int mt = 0; mt < 2; ++mt) {
                int row = warpM + mt*16 + (midx & 1)*8 + lrow;
                int ch  = kc*2 + (midx >> 1);
                uint32_t off = swz64((row << 6) + (ch << 4));
                LDMX4(ah[mt][0], ah[mt][1], ah[mt][2], ah[mt][3], sb + off);
                LDMX4(alr[mt][0], alr[mt][1], alr[mt][2], alr[mt][3], sb + 8192 + off);
            }
            // B fragments: x4 = (nLo kLo, nLo kHi, nHi kLo, nHi kHi) covering 16 n
            #pragma unroll
            for (int np = 0; np < 4; ++np) {
                int row = warpN + np*16 + (midx >> 1)*8 + lrow;
                int ch  = kc*2 + (midx & 1);
                uint32_t off = swz64((row << 6) + (ch << 4));
                LDMX4(bh[np][0], bh[np][1], bh[np][2], bh[np][3], sb + 16384 + off);
                LDMX4(blr[np][0], blr[np][1], blr[np][2], blr[np][3], sb + 24576 + off);
            }
            // term hi*hi
            #pragma unroll
            for (int mt = 0; mt < 2; ++mt)
                #pragma unroll
                for (int g = 0; g < 8; ++g)
                    MMA16816(acc[mt][g], ah[mt], bh[g>>1][(g&1)*2], bh[g>>1][(g&1)*2+1]);
            // term lo*hi
            #pragma unroll
            for (int mt = 0; mt < 2; ++mt)
                #pragma unroll
                for (int g = 0; g < 8; ++g)
                    MMA16816(acc[mt][g], alr[mt], bh[g>>1][(g&1)*2], bh[g>>1][(g&1)*2+1]);
            // term hi*lo
            #pragma unroll
            for (int mt = 0; mt < 2; ++mt)
                #pragma unroll
                for (int g = 0; g < 8; ++g)
                    MMA16816(acc[mt][g], ah[mt], blr[g>>1][(g&1)*2], blr[g>>1][(g&1)*2+1]);
        }
    }

    // epilogue
    const int crow  = m0 + warpM + (lane >> 2);
    const int ccol0 = n0 + warpN + (lane & 3) * 2;
    #pragma unroll
    for (int mt = 0; mt < 2; ++mt) {
        #pragma unroll
        for (int g = 0; g < 8; ++g) {
            int col = ccol0 + g * 8;
            float bx = __ldg(bias + col), by = __ldg(bias + col + 1);
            int r0 = crow + mt * 16;
            float2 v0 = make_float2(acc[mt][g][0] + bx, acc[mt][g][1] + by);
            float2 v1 = make_float2(acc[mt][g][2] + bx, acc[mt][g][3] + by);
            *(float2*)&C[(size_t)r0 * ldC + col]       = v0;
            *(float2*)&C[(size_t)(r0 + 8) * ldC + col] = v1;
        }
    }
}

// ---------------- warp-per-row LayerNorm + GELU (+ optional bf16 split out) ----------------
__global__ void ln_gelu(const float* __restrict__ in, float* __restrict__ out,
                        __nv_bfloat16* hi, __nv_bfloat16* lo,
                        const float* __restrict__ g, const float* __restrict__ b,
                        int rows, int width, int dogelu)
{
    int warp = (blockIdx.x * blockDim.x + threadIdx.x) >> 5;
    if (warp >= rows) return;
    int lane = threadIdx.x & 31;
    const float* rp = in + (size_t)warp * width;
    int nv = width >> 7;
    float vals[16];
    float s = 0.f, ss = 0.f;
    for (int i = 0; i < nv; i++) {
        float4 v = *(const float4*)(rp + lane*4 + i*128);
        vals[i*4+0]=v.x; vals[i*4+1]=v.y; vals[i*4+2]=v.z; vals[i*4+3]=v.w;
        s  += v.x + v.y + v.z + v.w;
        ss += v.x*v.x + v.y*v.y + v.z*v.z + v.w*v.w;
    }
    #pragma unroll
    for (int o = 16; o; o >>= 1) {
        s  += __shfl_xor_sync(0xffffffffu, s,  o);
        ss += __shfl_xor_sync(0xffffffffu, ss, o);
    }
    float inv_w = 1.f / (float)width;
    float mu = s * inv_w;
    float var = ss * inv_w - mu * mu;
    float r = rsqrtf(var + LN_EPS);
    float* op = out + (size_t)warp * width;
    for (int i = 0; i < nv; i++) {
        int f = lane*4 + i*128;
        float4 gg = *(const float4*)(g + f);
        float4 bb = *(const float4*)(b + f);
        float y0 = (vals[i*4+0]-mu)*r*gg.x + bb.x;
        float y1 = (vals[i*4+1]-mu)*r*gg.y + bb.y;
        float y2 = (vals[i*4+2]-mu)*r*gg.z + bb.z;
        float y3 = (vals[i*4+3]-mu)*r*gg.w + bb.w;
        if (dogelu) {
            y0 = 0.5f*y0*(1.f+erff(y0*0.70710678118654752f));
            y1 = 0.5f*y1*(1.f+erff(y1*0.70710678118654752f));
            y2 = 0.5f*y2*(1.f+erff(y2*0.70710678118654752f));
            y3 = 0.5f*y3*(1.f+erff(y3*0.70710678118654752f));
        }
        *(float4*)(op + f) = make_float4(y0, y1, y2, y3);
        if (hi) split_store4(hi, lo, (size_t)warp * width + f, y0, y1, y2, y3);
    }
}

// ---------------- residual + LN (+ optional GELU, + bf16 split out) ----------------
__global__ void resid_ln(const float* __restrict__ h, float* __restrict__ x,
                         __nv_bfloat16* hi, __nv_bfloat16* lo,
                         const float* __restrict__ bo, const float* __restrict__ g,
                         const float* __restrict__ b, int dogelu)
{
    int warp = (blockIdx.x * blockDim.x + threadIdx.x) >> 5;
    if (warp >= MROWS) return;
    int lane = threadIdx.x & 31;
    const float* hp = h + (size_t)warp * FDIM;
    float* xp = x + (size_t)warp * FDIM;
    float vals[16];
    float s = 0.f, ss = 0.f;
    #pragma unroll
    for (int i = 0; i < 4; i++) {
        int f = lane*4 + i*128;
        float4 hv = *(const float4*)(hp + f);
        float4 xv = *(const float4*)(xp + f);
        float4 bv = *(const float4*)(bo + f);
        float v0 = hv.x + bv.x + xv.x;
        float v1 = hv.y + bv.y + xv.y;
        float v2 = hv.z + bv.z + xv.z;
        float v3 = hv.w + bv.w + xv.w;
        vals[i*4+0]=v0; vals[i*4+1]=v1; vals[i*4+2]=v2; vals[i*4+3]=v3;
        s  += v0+v1+v2+v3;
        ss += v0*v0+v1*v1+v2*v2+v3*v3;
    }
    #pragma unroll
    for (int o = 16; o; o >>= 1) {
        s  += __shfl_xor_sync(0xffffffffu, s,  o);
        ss += __shfl_xor_sync(0xffffffffu, ss, o);
    }
    float mu = s * (1.f/FDIM);
    float var = ss * (1.f/FDIM) - mu*mu;
    float r = rsqrtf(var + LN_EPS);
    #pragma unroll
    for (int i = 0; i < 4; i++) {
        int f = lane*4 + i*128;
        float4 gg = *(const float4*)(g + f);
        float4 bb = *(const float4*)(b + f);
        float y0 = (vals[i*4+0]-mu)*r*gg.x + bb.x;
        float y1 = (vals[i*4+1]-mu)*r*gg.y + bb.y;
        float y2 = (vals[i*4+2]-mu)*r*gg.z + bb.z;
        float y3 = (vals[i*4+3]-mu)*r*gg.w + bb.w;
        if (dogelu) {
            y0 = 0.5f*y0*(1.f+erff(y0*0.70710678118654752f));
            y1 = 0.5f*y1*(1.f+erff(y1*0.70710678118654752f));
            y2 = 0.5f*y2*(1.f+erff(y2*0.70710678118654752f));
            y3 = 0.5f*y3*(1.f+erff(y3*0.70710678118654752f));
        }
        *(float4*)(xp + f) = make_float4(y0, y1, y2, y3);
        if (hi) split_store4(hi, lo, (size_t)warp * FDIM + f, y0, y1, y2, y3);
    }
}

// ---------------- GAT aggregation (xl/xr packed as [M,1024] = [xl|xr]) ----------------
__global__ __launch_bounds__(256) void gat(
    const float* __restrict__ xlr,
    const float* __restrict__ etype_emb,   // [3,4]
    const float* __restrict__ We,          // [4,512]
    const float* __restrict__ att,         // [4,128]
    float* __restrict__ hout)
{
    extern __shared__ char sm[];
    float* xls = (float*)sm;               // 80*512
    float* ee0 = xls + NNODE*FDIM;
    float* ee2 = ee0 + FDIM;
    const int b = blockIdx.x;
    const int tid = threadIdx.x;

    for (int f = tid; f < FDIM; f += 256) {
        float s0 = 0.f, s2 = 0.f;
        #pragma unroll
        for (int j = 0; j < 4; j++) {
            float w = We[j*FDIM + f];
            s0 += etype_emb[j]     * w;
            s2 += etype_emb[8 + j] * w;
        }
        ee0[f] = s0; ee2[f] = s2;
    }
    const float* xlb = xlr + (size_t)b * NNODE * 1024;
    for (int i4 = tid; i4 < NNODE*FDIM/4; i4 += 256) {
        int row = i4 >> 7, c4 = (i4 & 127) << 2;
        *(float4*)(xls + row*FDIM + c4) = *(const float4*)(xlb + (size_t)row*1024 + c4);
    }
    __syncthreads();

    const int lane = tid & 31, wid = tid >> 5;
    for (int t = wid; t < NNODE*HEADS; t += 8) {
        const int v = t >> 2, h = t & 3;
        const int base = h*CDIM + lane;
        const float* xrp = xlr + ((size_t)b*NNODE + v)*1024 + FDIM + base;
        float xrr[4], atr[4];
        #pragma unroll
        for (int j = 0; j < 4; j++) {
            xrr[j] = xrp[32*j];
            atr[j] = att[h*CDIM + lane + 32*j];
        }
        const int lo = (v < LMIR) ? 0 : LMIR;
        const int hi = (v < LMIR) ? (LMIR-1) : (NNODE-1);
        int   srcs[5];
        float c0[5], c2[5], valid[5];
        srcs[0]=v-1; srcs[1]=v+1; srcs[2]=v-2; srcs[3]=v+2; srcs[4]=v;
        valid[0] = (v-1 >= lo) ? 1.f : 0.f;
        valid[1] = (v+1 <= hi) ? 1.f : 0.f;
        valid[2] = (v-2 >= lo) ? 1.f : 0.f;
        valid[3] = (v+2 <= hi) ? 1.f : 0.f;
        valid[4] = 1.f;
        c0[0]=1.f; c2[0]=0.f;  c0[1]=1.f; c2[1]=0.f;
        c0[2]=0.f; c2[2]=1.f;  c0[3]=0.f; c2[3]=1.f;
        float n0 = valid[0] + valid[1];
        float n2 = valid[2] + valid[3];
        float inv = 1.f / (n0 + n2);
        c0[4] = n0 * inv; c2[4] = n2 * inv;
        #pragma unroll
        for (int e = 0; e < 5; e++) {
            int s = srcs[e];
            s = s < 0 ? 0 : (s > NNODE-1 ? NNODE-1 : s);
            srcs[e] = s;
        }
        float a[5];
        #pragma unroll
        for (int e = 0; e < 5; e++) {
            const float* xp = xls + srcs[e]*FDIM + base;
            float p = 0.f;
            #pragma unroll
            for (int j = 0; j < 4; j++) {
                int off = 32*j;
                float m = xp[off] + xrr[j] + c0[e]*ee0[base+off] + c2[e]*ee2[base+off];
                m = (m > 0.f) ? m : 0.2f*m;
                p += m * atr[j];
            }
            #pragma unroll
            for (int o = 16; o; o >>= 1) p += __shfl_xor_sync(0xffffffffu, p, o);
            a[e] = (valid[e] > 0.f) ? p : -1e30f;
        }
        float amax = a[0];
        #pragma unroll
        for (int e = 1; e < 5; e++) amax = fmaxf(amax, a[e]);
        float den = 0.f;
        #pragma unroll
        for (int e = 0; e < 5; e++) { a[e] = expf(a[e] - amax); den += a[e]; }
        float invd = 1.f / den;
        float o0=0.f, o1=0.f, o2=0.f, o3=0.f;
        #pragma unroll
        for (int e = 0; e < 5; e++) {
            float al = a[e] * invd;
            const float* xp = xls + srcs[e]*FDIM + base;
            o0 += al * xp[0];
            o1 += al * xp[32];
            o2 += al * xp[64];
            o3 += al * xp[96];
        }
        float* op = hout + ((size_t)b*NNODE + v)*FDIM + base;
        op[0]=o0; op[32]=o1; op[64]=o2; op[96]=o3;
    }
}

// ---------------- mean/max pool ----------------
__global__ void pool(const float* __restrict__ x, float* __restrict__ pooled) {
    int b = blockIdx.x;
    int f = threadIdx.x;
    const float* xp = x + (size_t)b * NNODE * FDIM + f;
    float s = 0.f, mx = -3.4e38f;
    #pragma unroll 4
    for (int v = 0; v < NNODE; v++) {
        float val = xp[(size_t)v * FDIM];
        s += val;
        mx = fmaxf(mx, val);
    }
    pooled[(size_t)b*2*FDIM + f]        = s * (1.f/NNODE);
    pooled[(size_t)b*2*FDIM + FDIM + f] = mx;
}

// ---------------- head GEMM (tiny, fp32) ----------------
__global__ __launch_bounds__(128) void gemm_out(
    const float* __restrict__ A, const float* __restrict__ Bw,
    const float* __restrict__ bias, float* __restrict__ C)
{
    __shared__ float As[8][1024];
    const int r0 = blockIdx.x * 8;
    const int tid = threadIdx.x;
    for (int i4 = tid; i4 < 8*1024/4; i4 += 128)
        *(float4*)(&As[0][0] + (size_t)i4*4) = *(const float4*)(A + (size_t)r0*1024 + (size_t)i4*4);
    __syncthreads();
    float acc[8];
    #pragma unroll
    for (int r = 0; r < 8; r++) acc[r] = 0.f;
    #pragma unroll 4
    for (int k = 0; k < 1024; k++) {
        float bv = Bw[(size_t)k*128 + tid];
        #pragma unroll
        for (int r = 0; r < 8; r++) acc[r] += As[r][k] * bv;
    }
    float bi = bias[tid];
    #pragma unroll
    for (int r = 0; r < 8; r++)
        C[(size_t)(r0 + r)*128 + tid] = acc[r] + bi;
}

// ---------------- launch ----------------
extern "C" void kernel_launch(void* const* d_in, const int* in_sizes, int n_in,
                              void* d_out, int out_size) {
    const float* mirna  = (const float*)d_in[0];
    const float* target = (const float*)d_in[1];
    const float* ntype  = (const float*)d_in[2];
    const float* etype  = (const float*)d_in[3];
    const float* in_W   = (const float*)d_in[4];
    const float* in_b   = (const float*)d_in[5];
    const float* in_lng = (const float*)d_in[6];
    const float* in_lnb = (const float*)d_in[7];
    const float* Wl     = (const float*)d_in[8];
    const float* bl     = (const float*)d_in[9];
    const float* Wr     = (const float*)d_in[10];
    const float* br     = (const float*)d_in[11];
    const float* We     = (const float*)d_in[12];
    const float* attw   = (const float*)d_in[13];
    const float* bo     = (const float*)d_in[14];
    const float* lng    = (const float*)d_in[15];
    const float* lnb    = (const float*)d_in[16];
    const float* outW   = (const float*)d_in[17];
    const float* outb   = (const float*)d_in[18];
    const float* olng   = (const float*)d_in[19];
    const float* olnb   = (const float*)d_in[20];
    float* out = (float*)d_out;

    float *xp, *xlrp, *hp, *poolp, *op, *bcatp;
    __nv_bfloat16 *x0hp, *x0lp, *wihp, *wilp, *wchp, *wclp, *xhp, *xlop;
    cudaGetSymbolAddress((void**)&x0hp, g_x0h);
    cudaGetSymbolAddress((void**)&x0lp, g_x0l);
    cudaGetSymbolAddress((void**)&wihp, g_wih);
    cudaGetSymbolAddress((void**)&wilp, g_wil);
    cudaGetSymbolAddress((void**)&wchp, g_wch);
    cudaGetSymbolAddress((void**)&wclp, g_wcl);
    cudaGetSymbolAddress((void**)&bcatp, g_bcat);
    cudaGetSymbolAddress((void**)&xp,    g_x);
    cudaGetSymbolAddress((void**)&xhp,   g_xh);
    cudaGetSymbolAddress((void**)&xlop,  g_xlo);
    cudaGetSymbolAddress((void**)&xlrp,  g_xlr);
    cudaGetSymbolAddress((void**)&hp,    g_h);
    cudaGetSymbolAddress((void**)&poolp, g_pool);
    cudaGetSymbolAddress((void**)&op,    g_o);

    const int GAT_SMEM = (NNODE*FDIM + 2*FDIM) * sizeof(float);
    cudaFuncSetAttribute(gat, cudaFuncAttributeMaxDynamicSharedMemorySize, GAT_SMEM);
    cudaFuncSetAttribute(gemm_bf16, cudaFuncAttributeMaxDynamicSharedMemorySize, GEMM_SMEM);

    // weights prep + x0 build
    const int PREP_T = FDIM*NDIM + 2*1024*FDIM + 2*1024;
    prep_weights<<<(PREP_T + 255)/256, 256>>>(in_W, Wl, Wr, bl, br);
    build_x0<<<(MROWS*64 + 255)/256, 256>>>(mirna, target, ntype);

    // input projection (M=81920, N=512, K=256)
    gemm_bf16<<<dim3(FDIM/BN, MROWS/BM), 256, GEMM_SMEM>>>(
        x0hp, x0lp, wihp, wilp, in_b, hp, NDIM);
    ln_gelu<<<(MROWS*32 + 255)/256, 256>>>(hp, xp, xhp, xlop, in_lng, in_lnb, MROWS, FDIM, 1);

    // GAT layers: fused [Wl|Wr] GEMM (M=81920, N=1024, K=512)
    for (int i = 0; i < 2; i++) {
        gemm_bf16<<<dim3(1024/BN, MROWS/BM), 256, GEMM_SMEM>>>(
            xhp, xlop, wchp + (size_t)i*1024*FDIM, wclp + (size_t)i*1024*FDIM,
            bcatp + (size_t)i*1024, xlrp, FDIM);
        gat<<<BSZ, 256, GAT_SMEM>>>(xlrp, etype,
                                    We + (size_t)i*HEADS*FDIM,
                                    attw + (size_t)i*HEADS*CDIM, hp);
        resid_ln<<<(MROWS*32 + 255)/256, 256>>>(hp, xp, xhp, xlop,
                                                bo + (size_t)i*FDIM,
                                                lng + (size_t)i*FDIM, lnb + (size_t)i*FDIM,
                                                (i == 0) ? 1 : 0);
    }

    // pool + head
    pool<<<BSZ, FDIM>>>(xp, poolp);
    gemm_out<<<BSZ/8, 128>>>(poolp, outW, outb, op);
    ln_gelu<<<(BSZ*32 + 255)/256, 256>>>(op, out, (__nv_bfloat16*)nullptr, (__nv_bfloat16*)nullptr,
                                         olng, olnb, BSZ, OUTD, 1);
}

// round 5
// speedup vs baseline: 2.0189x; 1.0547x over previous
#include <cuda_runtime.h>
#include <cuda_bf16.h>
#include <math.h>
#include <stdint.h>

// ---------------- problem constants ----------------
#define BSZ    1024
#define NNODE  80
#define LMIR   30
#define NDIM   256
#define FDIM   512
#define HEADS  4
#define CDIM   128
#define OUTD   128
#define MROWS  (BSZ*NNODE)       // 81920
#define LN_EPS 1e-5f

// GEMM tiling (mma.sync; CTA 128x256, warp grid 2x4, warp tile 64x64)
#define BM 128
#define BN 256
#define BKK 32
#define NSTG 3
#define STG_BYTES 49152                 // A hi/lo 16KB + B hi/lo 32KB
#define GEMM_SMEM (NSTG*STG_BYTES)      // 144KB

// ---------------- device scratch ----------------
__device__ __nv_bfloat16 g_x0h [(size_t)MROWS*NDIM];
__device__ __nv_bfloat16 g_x0l [(size_t)MROWS*NDIM];
__device__ __nv_bfloat16 g_wih [(size_t)FDIM*NDIM];        // in_W^T [N=512, K=256]
__device__ __nv_bfloat16 g_wil [(size_t)FDIM*NDIM];
__device__ __nv_bfloat16 g_wch [(size_t)2*1024*FDIM];      // concat(Wl,Wr)^T per layer [N=1024,K=512]
__device__ __nv_bfloat16 g_wcl [(size_t)2*1024*FDIM];
__device__ float         g_bcat[(size_t)2*1024];
__device__ float         g_x   [(size_t)MROWS*FDIM];       // node features fp32
__device__ __nv_bfloat16 g_xh  [(size_t)MROWS*FDIM];       // x hi
__device__ __nv_bfloat16 g_xlo [(size_t)MROWS*FDIM];       // x lo
__device__ float         g_xlr [(size_t)MROWS*1024];       // [xl | xr] per layer
__device__ float         g_h   [(size_t)MROWS*FDIM];       // GEMM1 out / GAT out
__device__ float         g_pool[(size_t)BSZ*2*FDIM];
__device__ float         g_o   [(size_t)BSZ*OUTD];

// ---------------- PTX helpers ----------------
__device__ __forceinline__ uint32_t smem_u32(const void* p) {
    uint32_t a;
    asm("{ .reg .u64 t; cvta.to.shared.u64 t, %1; cvt.u32.u64 %0, t; }" : "=r"(a) : "l"(p));
    return a;
}
__device__ __forceinline__ void cp16(uint32_t saddr, const void* gaddr) {
    asm volatile("cp.async.cg.shared.global [%0], [%1], 16;" :: "r"(saddr), "l"(gaddr));
}
#define CP_COMMIT() asm volatile("cp.async.commit_group;" ::: "memory")

// SW64 swizzle: bits[5:4] ^= bits[8:7]  (conflict-free ldmatrix on 64B rows)
__device__ __forceinline__ uint32_t swz64(uint32_t off) { return off ^ ((off >> 3) & 0x30); }

#define LDMX4(r0,r1,r2,r3,a) \
    asm volatile("ldmatrix.sync.aligned.m8n8.x4.shared.b16 {%0,%1,%2,%3}, [%4];" \
        : "=r"(r0), "=r"(r1), "=r"(r2), "=r"(r3) : "r"(a))

#define MMA16816(c, a, b0, b1) \
    asm volatile("mma.sync.aligned.m16n8k16.row.col.f32.bf16.bf16.f32 " \
        "{%0,%1,%2,%3}, {%4,%5,%6,%7}, {%8,%9}, {%0,%1,%2,%3};" \
        : "+f"((c)[0]), "+f"((c)[1]), "+f"((c)[2]), "+f"((c)[3]) \
        : "r"((a)[0]), "r"((a)[1]), "r"((a)[2]), "r"((a)[3]), "r"(b0), "r"(b1))

// ---------------- bf16 split helpers ----------------
__device__ __forceinline__ void split_store4(__nv_bfloat16* hi, __nv_bfloat16* lo, size_t off,
                                             float a, float b, float c, float d) {
    __nv_bfloat16 h0 = __float2bfloat16_rn(a), h1 = __float2bfloat16_rn(b);
    __nv_bfloat16 h2 = __float2bfloat16_rn(c), h3 = __float2bfloat16_rn(d);
    __nv_bfloat16 l0 = __float2bfloat16_rn(a - __bfloat162float(h0));
    __nv_bfloat16 l1 = __float2bfloat16_rn(b - __bfloat162float(h1));
    __nv_bfloat16 l2 = __float2bfloat16_rn(c - __bfloat162float(h2));
    __nv_bfloat16 l3 = __float2bfloat16_rn(d - __bfloat162float(h3));
    ushort4 hv, lv;
    hv.x = *(unsigned short*)&h0; hv.y = *(unsigned short*)&h1; hv.z = *(unsigned short*)&h2; hv.w = *(unsigned short*)&h3;
    lv.x = *(unsigned short*)&l0; lv.y = *(unsigned short*)&l1; lv.z = *(unsigned short*)&l2; lv.w = *(unsigned short*)&l3;
    *(ushort4*)(hi + off) = hv;
    *(ushort4*)(lo + off) = lv;
}

// ---------------- weight prep: transpose + split ----------------
__global__ void prep_weights(const float* __restrict__ in_W,
                             const float* __restrict__ Wl, const float* __restrict__ Wr,
                             const float* __restrict__ bl, const float* __restrict__ br) {
    const int T0 = FDIM * NDIM;            // 131072
    const int T1 = 2 * 1024 * FDIM;        // 1048576
    int t = blockIdx.x * blockDim.x + threadIdx.x;
    if (t < T0) {
        int n = t / NDIM, k = t % NDIM;
        float v = in_W[(size_t)k * FDIM + n];
        __nv_bfloat16 h = __float2bfloat16_rn(v);
        g_wih[t] = h;
        g_wil[t] = __float2bfloat16_rn(v - __bfloat162float(h));
        return;
    }
    t -= T0;
    if (t < T1) {
        int i = t / (1024 * FDIM);
        int r = t % (1024 * FDIM);
        int n = r / FDIM, k = r % FDIM;
        float v = (n < FDIM) ? Wl[(size_t)i*FDIM*FDIM + (size_t)k*FDIM + n]
                             : Wr[(size_t)i*FDIM*FDIM + (size_t)k*FDIM + (n - FDIM)];
        __nv_bfloat16 h = __float2bfloat16_rn(v);
        g_wch[t] = h;
        g_wcl[t] = __float2bfloat16_rn(v - __bfloat162float(h));
        return;
    }
    t -= T1;
    if (t < 2 * 1024) {
        int i = t / 1024, n = t % 1024;
        g_bcat[t] = (n < FDIM) ? bl[i*FDIM + n] : br[i*FDIM + (n - FDIM)];
    }
}

// ---------------- build x0 (hi/lo bf16 directly) ----------------
__global__ void build_x0(const float* __restrict__ mirna,
                         const float* __restrict__ target,
                         const float* __restrict__ ntype) {
    int i4 = blockIdx.x * blockDim.x + threadIdx.x;
    if (i4 >= MROWS * (NDIM / 4)) return;
    int row = i4 >> 6;
    int c4  = (i4 & 63) << 2;
    int b = row / NNODE, v = row % NNODE;
    const float* src; const float* emb;
    if (v < LMIR) { src = mirna  + ((size_t)b*LMIR + v) * NDIM;                emb = ntype; }
    else          { src = target + ((size_t)b*(NNODE-LMIR) + (v-LMIR)) * NDIM; emb = ntype + NDIM; }
    float4 a = *(const float4*)(src + c4);
    float4 e = *(const float4*)(emb + c4);
    split_store4(g_x0h, g_x0l, (size_t)row*NDIM + c4, a.x+e.x, a.y+e.y, a.z+e.z, a.w+e.w);
}

// ---------------- bf16 3-term split GEMM via mma.sync ----------------
// D[M,N] = A[M,K] @ B^T + bias;  A row-major [M,K], B row-major [N,K].
// grid (N/256, M/128), 256 threads = 8 warps (2 M-groups x 4 N-groups), warp tile 64x64.
__global__ __launch_bounds__(256) void gemm_bf16(
    const __nv_bfloat16* __restrict__ Ah, const __nv_bfloat16* __restrict__ Al,
    const __nv_bfloat16* __restrict__ Bh, const __nv_bfloat16* __restrict__ Bl,
    const float* __restrict__ bias, float* __restrict__ C, int K)
{
    extern __shared__ char sm[];
    const uint32_t smem_base = smem_u32(sm);
    const int tid = threadIdx.x;
    const int wid = tid >> 5, lane = tid & 31;
    const int m0 = blockIdx.y * BM;
    const int n0 = blockIdx.x * BN;
    const int ldC = gridDim.x * BN;
    const int nchunk = K >> 5;              // K per stage = 32
    const int warpM = (wid & 1) * 64;
    const int warpN = (wid >> 1) * 64;
    const int lrow = lane & 7, midx = lane >> 3;

    float acc[4][8][4];                      // [m16 tile][n8 col][frag]
    #pragma unroll
    for (int i = 0; i < 4; i++)
        #pragma unroll
        for (int j = 0; j < 8; j++)
            #pragma unroll
            for (int q = 0; q < 4; q++) acc[i][j][q] = 0.f;

    const __nv_bfloat16* Abase[2] = { Ah + (size_t)m0 * K, Al + (size_t)m0 * K };
    const __nv_bfloat16* Bbase[2] = { Bh + (size_t)n0 * K, Bl + (size_t)n0 * K };

    // stage layout: [Ah 8KB][Al 8KB][Bh 16KB][Bl 16KB]
    auto load_stage = [&](int slot, int c) {
        const uint32_t sb = smem_base + slot * STG_BYTES;
        const int k0 = c * BKK;
        #pragma unroll
        for (int i = 0; i < 12; i++) {
            int idx = tid + i * 256;              // 0..3071
            if (idx < 1024) {                      // A hi/lo: 2 x 512 chunks
                int sub = idx >> 9, w = idx & 511;
                int row = w >> 2, ch = w & 3;
                cp16(sb + (sub << 13) + swz64((row << 6) + (ch << 4)),
                     Abase[sub] + (size_t)row * K + k0 + ch * 8);
            } else {                               // B hi/lo: 2 x 1024 chunks
                int w = idx - 1024;
                int sub = w >> 10; w &= 1023;
                int row = w >> 2, ch = w & 3;
                cp16(sb + 16384 + (sub << 14) + swz64((row << 6) + (ch << 4)),
                     Bbase[sub] + (size_t)row * K + k0 + ch * 8);
            }
        }
        CP_COMMIT();
    };

    load_stage(0, 0);
    load_stage(1, 1);

    for (int c = 0; c < nchunk; ++c) {
        if (c < nchunk - 1) asm volatile("cp.async.wait_group 1;" ::: "memory");
        else                asm volatile("cp.async.wait_group 0;" ::: "memory");
        __syncthreads();
        if (c + 2 < nchunk) load_stage((c + 2) % NSTG, c + 2);

        const uint32_t sb = smem_base + (c % NSTG) * STG_BYTES;
        #pragma unroll
        for (int kc = 0; kc < 2; ++kc) {          // two k16 steps per stage
            // B fragments first (shared across all mt)
            uint32_t bh[4][4], blr[4][4];
            #pragma unroll
            for (int np = 0; np < 4; ++np) {
                int row = warpN + np*16 + (midx >> 1)*8 + lrow;
                int ch  = kc*2 + (midx & 1);
                uint32_t off = swz64((row << 6) + (ch << 4));
                LDMX4(bh[np][0],  bh[np][1],  bh[np][2],  bh[np][3],  sb + 16384 + off);
                LDMX4(blr[np][0], blr[np][1], blr[np][2], blr[np][3], sb + 32768 + off);
            }
            // per m16 tile: load A frags, run 24 MMAs
            #pragma unroll
            for (int mt = 0; mt < 4; ++mt) {
                int row = warpM + mt*16 + (midx & 1)*8 + lrow;
                int ch  = kc*2 + (midx >> 1);
                uint32_t off = swz64((row << 6) + (ch << 4));
                uint32_t ah[4], alr[4];
                LDMX4(ah[0], ah[1], ah[2], ah[3], sb + off);
                LDMX4(alr[0], alr[1], alr[2], alr[3], sb + 8192 + off);
                #pragma unroll
                for (int g = 0; g < 8; ++g)
                    MMA16816(acc[mt][g], ah, bh[g>>1][(g&1)*2], bh[g>>1][(g&1)*2+1]);
                #pragma unroll
                for (int g = 0; g < 8; ++g)
                    MMA16816(acc[mt][g], alr, bh[g>>1][(g&1)*2], bh[g>>1][(g&1)*2+1]);
                #pragma unroll
                for (int g = 0; g < 8; ++g)
                    MMA16816(acc[mt][g], ah, blr[g>>1][(g&1)*2], blr[g>>1][(g&1)*2+1]);
            }
        }
    }

    // epilogue
    const int crow  = m0 + warpM + (lane >> 2);
    const int ccol0 = n0 + warpN + (lane & 3) * 2;
    #pragma unroll
    for (int mt = 0; mt < 4; ++mt) {
        #pragma unroll
        for (int g = 0; g < 8; ++g) {
            int col = ccol0 + g * 8;
            float bx = __ldg(bias + col), by = __ldg(bias + col + 1);
            int r0 = crow + mt * 16;
            float2 v0 = make_float2(acc[mt][g][0] + bx, acc[mt][g][1] + by);
            float2 v1 = make_float2(acc[mt][g][2] + bx, acc[mt][g][3] + by);
            *(float2*)&C[(size_t)r0 * ldC + col]       = v0;
            *(float2*)&C[(size_t)(r0 + 8) * ldC + col] = v1;
        }
    }
}

// ---------------- warp-per-row LayerNorm + GELU (+ optional bf16 split out) ----------------
__global__ void ln_gelu(const float* __restrict__ in, float* __restrict__ out,
                        __nv_bfloat16* hi, __nv_bfloat16* lo,
                        const float* __restrict__ g, const float* __restrict__ b,
                        int rows, int width, int dogelu)
{
    int warp = (blockIdx.x * blockDim.x + threadIdx.x) >> 5;
    if (warp >= rows) return;
    int lane = threadIdx.x & 31;
    const float* rp = in + (size_t)warp * width;
    int nv = width >> 7;
    float vals[16];
    float s = 0.f, ss = 0.f;
    for (int i = 0; i < nv; i++) {
        float4 v = *(const float4*)(rp + lane*4 + i*128);
        vals[i*4+0]=v.x; vals[i*4+1]=v.y; vals[i*4+2]=v.z; vals[i*4+3]=v.w;
        s  += v.x + v.y + v.z + v.w;
        ss += v.x*v.x + v.y*v.y + v.z*v.z + v.w*v.w;
    }
    #pragma unroll
    for (int o = 16; o; o >>= 1) {
        s  += __shfl_xor_sync(0xffffffffu, s,  o);
        ss += __shfl_xor_sync(0xffffffffu, ss, o);
    }
    float inv_w = 1.f / (float)width;
    float mu = s * inv_w;
    float var = ss * inv_w - mu * mu;
    float r = rsqrtf(var + LN_EPS);
    float* op = out + (size_t)warp * width;
    for (int i = 0; i < nv; i++) {
        int f = lane*4 + i*128;
        float4 gg = *(const float4*)(g + f);
        float4 bb = *(const float4*)(b + f);
        float y0 = (vals[i*4+0]-mu)*r*gg.x + bb.x;
        float y1 = (vals[i*4+1]-mu)*r*gg.y + bb.y;
        float y2 = (vals[i*4+2]-mu)*r*gg.z + bb.z;
        float y3 = (vals[i*4+3]-mu)*r*gg.w + bb.w;
        if (dogelu) {
            y0 = 0.5f*y0*(1.f+erff(y0*0.70710678118654752f));
            y1 = 0.5f*y1*(1.f+erff(y1*0.70710678118654752f));
            y2 = 0.5f*y2*(1.f+erff(y2*0.70710678118654752f));
            y3 = 0.5f*y3*(1.f+erff(y3*0.70710678118654752f));
        }
        *(float4*)(op + f) = make_float4(y0, y1, y2, y3);
        if (hi) split_store4(hi, lo, (size_t)warp * width + f, y0, y1, y2, y3);
    }
}

// ---------------- residual + LN (+ optional GELU, + bf16 split out) ----------------
__global__ void resid_ln(const float* __restrict__ h, float* __restrict__ x,
                         __nv_bfloat16* hi, __nv_bfloat16* lo,
                         const float* __restrict__ bo, const float* __restrict__ g,
                         const float* __restrict__ b, int dogelu)
{
    int warp = (blockIdx.x * blockDim.x + threadIdx.x) >> 5;
    if (warp >= MROWS) return;
    int lane = threadIdx.x & 31;
    const float* hp = h + (size_t)warp * FDIM;
    float* xp = x + (size_t)warp * FDIM;
    float vals[16];
    float s = 0.f, ss = 0.f;
    #pragma unroll
    for (int i = 0; i < 4; i++) {
        int f = lane*4 + i*128;
        float4 hv = *(const float4*)(hp + f);
        float4 xv = *(const float4*)(xp + f);
        float4 bv = *(const float4*)(bo + f);
        float v0 = hv.x + bv.x + xv.x;
        float v1 = hv.y + bv.y + xv.y;
        float v2 = hv.z + bv.z + xv.z;
        float v3 = hv.w + bv.w + xv.w;
        vals[i*4+0]=v0; vals[i*4+1]=v1; vals[i*4+2]=v2; vals[i*4+3]=v3;
        s  += v0+v1+v2+v3;
        ss += v0*v0+v1*v1+v2*v2+v3*v3;
    }
    #pragma unroll
    for (int o = 16; o; o >>= 1) {
        s  += __shfl_xor_sync(0xffffffffu, s,  o);
        ss += __shfl_xor_sync(0xffffffffu, ss, o);
    }
    float mu = s * (1.f/FDIM);
    float var = ss * (1.f/FDIM) - mu*mu;
    float r = rsqrtf(var + LN_EPS);
    #pragma unroll
    for (int i = 0; i < 4; i++) {
        int f = lane*4 + i*128;
        float4 gg = *(const float4*)(g + f);
        float4 bb = *(const float4*)(b + f);
        float y0 = (vals[i*4+0]-mu)*r*gg.x + bb.x;
        float y1 = (vals[i*4+1]-mu)*r*gg.y + bb.y;
        float y2 = (vals[i*4+2]-mu)*r*gg.z + bb.z;
        float y3 = (vals[i*4+3]-mu)*r*gg.w + bb.w;
        if (dogelu) {
            y0 = 0.5f*y0*(1.f+erff(y0*0.70710678118654752f));
            y1 = 0.5f*y1*(1.f+erff(y1*0.70710678118654752f));
            y2 = 0.5f*y2*(1.f+erff(y2*0.70710678118654752f));
            y3 = 0.5f*y3*(1.f+erff(y3*0.70710678118654752f));
        }
        *(float4*)(xp + f) = make_float4(y0, y1, y2, y3);
        if (hi) split_store4(hi, lo, (size_t)warp * FDIM + f, y0, y1, y2, y3);
    }
}

// ---------------- GAT aggregation (xl/xr packed as [M,1024] = [xl|xr]) ----------------
__global__ __launch_bounds__(256) void gat(
    const float* __restrict__ xlr,
    const float* __restrict__ etype_emb,   // [3,4]
    const float* __restrict__ We,          // [4,512]
    const float* __restrict__ att,         // [4,128]
    float* __restrict__ hout)
{
    extern __shared__ char sm[];
    float* xls = (float*)sm;               // 80*512
    float* ee0 = xls + NNODE*FDIM;
    float* ee2 = ee0 + FDIM;
    const int b = blockIdx.x;
    const int tid = threadIdx.x;

    for (int f = tid; f < FDIM; f += 256) {
        float s0 = 0.f, s2 = 0.f;
        #pragma unroll
        for (int j = 0; j < 4; j++) {
            float w = We[j*FDIM + f];
            s0 += etype_emb[j]     * w;
            s2 += etype_emb[8 + j] * w;
        }
        ee0[f] = s0; ee2[f] = s2;
    }
    const float* xlb = xlr + (size_t)b * NNODE * 1024;
    for (int i4 = tid; i4 < NNODE*FDIM/4; i4 += 256) {
        int row = i4 >> 7, c4 = (i4 & 127) << 2;
        *(float4*)(xls + row*FDIM + c4) = *(const float4*)(xlb + (size_t)row*1024 + c4);
    }
    __syncthreads();

    const int lane = tid & 31, wid = tid >> 5;
    for (int t = wid; t < NNODE*HEADS; t += 8) {
        const int v = t >> 2, h = t & 3;
        const int base = h*CDIM + lane;
        const float* xrp = xlr + ((size_t)b*NNODE + v)*1024 + FDIM + base;
        float xrr[4], atr[4];
        #pragma unroll
        for (int j = 0; j < 4; j++) {
            xrr[j] = xrp[32*j];
            atr[j] = att[h*CDIM + lane + 32*j];
        }
        const int lo = (v < LMIR) ? 0 : LMIR;
        const int hi = (v < LMIR) ? (LMIR-1) : (NNODE-1);
        int   srcs[5];
        float c0[5], c2[5], valid[5];
        srcs[0]=v-1; srcs[1]=v+1; srcs[2]=v-2; srcs[3]=v+2; srcs[4]=v;
        valid[0] = (v-1 >= lo) ? 1.f : 0.f;
        valid[1] = (v+1 <= hi) ? 1.f : 0.f;
        valid[2] = (v-2 >= lo) ? 1.f : 0.f;
        valid[3] = (v+2 <= hi) ? 1.f : 0.f;
        valid[4] = 1.f;
        c0[0]=1.f; c2[0]=0.f;  c0[1]=1.f; c2[1]=0.f;
        c0[2]=0.f; c2[2]=1.f;  c0[3]=0.f; c2[3]=1.f;
        float n0 = valid[0] + valid[1];
        float n2 = valid[2] + valid[3];
        float inv = 1.f / (n0 + n2);
        c0[4] = n0 * inv; c2[4] = n2 * inv;
        #pragma unroll
        for (int e = 0; e < 5; e++) {
            int s = srcs[e];
            s = s < 0 ? 0 : (s > NNODE-1 ? NNODE-1 : s);
            srcs[e] = s;
        }
        float a[5];
        #pragma unroll
        for (int e = 0; e < 5; e++) {
            const float* xp = xls + srcs[e]*FDIM + base;
            float p = 0.f;
            #pragma unroll
            for (int j = 0; j < 4; j++) {
                int off = 32*j;
                float m = xp[off] + xrr[j] + c0[e]*ee0[base+off] + c2[e]*ee2[base+off];
                m = (m > 0.f) ? m : 0.2f*m;
                p += m * atr[j];
            }
            #pragma unroll
            for (int o = 16; o; o >>= 1) p += __shfl_xor_sync(0xffffffffu, p, o);
            a[e] = (valid[e] > 0.f) ? p : -1e30f;
        }
        float amax = a[0];
        #pragma unroll
        for (int e = 1; e < 5; e++) amax = fmaxf(amax, a[e]);
        float den = 0.f;
        #pragma unroll
        for (int e = 0; e < 5; e++) { a[e] = expf(a[e] - amax); den += a[e]; }
        float invd = 1.f / den;
        float o0=0.f, o1=0.f, o2=0.f, o3=0.f;
        #pragma unroll
        for (int e = 0; e < 5; e++) {
            float al = a[e] * invd;
            const float* xp = xls + srcs[e]*FDIM + base;
            o0 += al * xp[0];
            o1 += al * xp[32];
            o2 += al * xp[64];
            o3 += al * xp[96];
        }
        float* op = hout + ((size_t)b*NNODE + v)*FDIM + base;
        op[0]=o0; op[32]=o1; op[64]=o2; op[96]=o3;
    }
}

// ---------------- mean/max pool ----------------
__global__ void pool(const float* __restrict__ x, float* __restrict__ pooled) {
    int b = blockIdx.x;
    int f = threadIdx.x;
    const float* xp = x + (size_t)b * NNODE * FDIM + f;
    float s = 0.f, mx = -3.4e38f;
    #pragma unroll 4
    for (int v = 0; v < NNODE; v++) {
        float val = xp[(size_t)v * FDIM];
        s += val;
        mx = fmaxf(mx, val);
    }
    pooled[(size_t)b*2*FDIM + f]        = s * (1.f/NNODE);
    pooled[(size_t)b*2*FDIM + FDIM + f] = mx;
}

// ---------------- head GEMM (tiny, fp32) ----------------
__global__ __launch_bounds__(128) void gemm_out(
    const float* __restrict__ A, const float* __restrict__ Bw,
    const float* __restrict__ bias, float* __restrict__ C)
{
    __shared__ float As[8][1024];
    const int r0 = blockIdx.x * 8;
    const int tid = threadIdx.x;
    for (int i4 = tid; i4 < 8*1024/4; i4 += 128)
        *(float4*)(&As[0][0] + (size_t)i4*4) = *(const float4*)(A + (size_t)r0*1024 + (size_t)i4*4);
    __syncthreads();
    float acc[8];
    #pragma unroll
    for (int r = 0; r < 8; r++) acc[r] = 0.f;
    #pragma unroll 4
    for (int k = 0; k < 1024; k++) {
        float bv = Bw[(size_t)k*128 + tid];
        #pragma unroll
        for (int r = 0; r < 8; r++) acc[r] += As[r][k] * bv;
    }
    float bi = bias[tid];
    #pragma unroll
    for (int r = 0; r < 8; r++)
        C[(size_t)(r0 + r)*128 + tid] = acc[r] + bi;
}

// ---------------- launch ----------------
extern "C" void kernel_launch(void* const* d_in, const int* in_sizes, int n_in,
                              void* d_out, int out_size) {
    const float* mirna  = (const float*)d_in[0];
    const float* target = (const float*)d_in[1];
    const float* ntype  = (const float*)d_in[2];
    const float* etype  = (const float*)d_in[3];
    const float* in_W   = (const float*)d_in[4];
    const float* in_b   = (const float*)d_in[5];
    const float* in_lng = (const float*)d_in[6];
    const float* in_lnb = (const float*)d_in[7];
    const float* Wl     = (const float*)d_in[8];
    const float* bl     = (const float*)d_in[9];
    const float* Wr     = (const float*)d_in[10];
    const float* br     = (const float*)d_in[11];
    const float* We     = (const float*)d_in[12];
    const float* attw   = (const float*)d_in[13];
    const float* bo     = (const float*)d_in[14];
    const float* lng    = (const float*)d_in[15];
    const float* lnb    = (const float*)d_in[16];
    const float* outW   = (const float*)d_in[17];
    const float* outb   = (const float*)d_in[18];
    const float* olng   = (const float*)d_in[19];
    const float* olnb   = (const float*)d_in[20];
    float* out = (float*)d_out;

    float *xp, *xlrp, *hp, *poolp, *op, *bcatp;
    __nv_bfloat16 *x0hp, *x0lp, *wihp, *wilp, *wchp, *wclp, *xhp, *xlop;
    cudaGetSymbolAddress((void**)&x0hp, g_x0h);
    cudaGetSymbolAddress((void**)&x0lp, g_x0l);
    cudaGetSymbolAddress((void**)&wihp, g_wih);
    cudaGetSymbolAddress((void**)&wilp, g_wil);
    cudaGetSymbolAddress((void**)&wchp, g_wch);
    cudaGetSymbolAddress((void**)&wclp, g_wcl);
    cudaGetSymbolAddress((void**)&bcatp, g_bcat);
    cudaGetSymbolAddress((void**)&xp,    g_x);
    cudaGetSymbolAddress((void**)&xhp,   g_xh);
    cudaGetSymbolAddress((void**)&xlop,  g_xlo);
    cudaGetSymbolAddress((void**)&xlrp,  g_xlr);
    cudaGetSymbolAddress((void**)&hp,    g_h);
    cudaGetSymbolAddress((void**)&poolp, g_pool);
    cudaGetSymbolAddress((void**)&op,    g_o);

    const int GAT_SMEM = (NNODE*FDIM + 2*FDIM) * sizeof(float);
    cudaFuncSetAttribute(gat, cudaFuncAttributeMaxDynamicSharedMemorySize, GAT_SMEM);
    cudaFuncSetAttribute(gemm_bf16, cudaFuncAttributeMaxDynamicSharedMemorySize, GEMM_SMEM);

    // weights prep + x0 build
    const int PREP_T = FDIM*NDIM + 2*1024*FDIM + 2*1024;
    prep_weights<<<(PREP_T + 255)/256, 256>>>(in_W, Wl, Wr, bl, br);
    build_x0<<<(MROWS*64 + 255)/256, 256>>>(mirna, target, ntype);

    // input projection (M=81920, N=512, K=256)
    gemm_bf16<<<dim3(FDIM/BN, MROWS/BM), 256, GEMM_SMEM>>>(
        x0hp, x0lp, wihp, wilp, in_b, hp, NDIM);
    ln_gelu<<<(MROWS*32 + 255)/256, 256>>>(hp, xp, xhp, xlop, in_lng, in_lnb, MROWS, FDIM, 1);

    // GAT layers: fused [Wl|Wr] GEMM (M=81920, N=1024, K=512)
    for (int i = 0; i < 2; i++) {
        gemm_bf16<<<dim3(1024/BN, MROWS/BM), 256, GEMM_SMEM>>>(
            xhp, xlop, wchp + (size_t)i*1024*FDIM, wclp + (size_t)i*1024*FDIM,
            bcatp + (size_t)i*1024, xlrp, FDIM);
        gat<<<BSZ, 256, GAT_SMEM>>>(xlrp, etype,
                                    We + (size_t)i*HEADS*FDIM,
                                    attw + (size_t)i*HEADS*CDIM, hp);
        resid_ln<<<(MROWS*32 + 255)/256, 256>>>(hp, xp, xhp, xlop,
                                                bo + (size_t)i*FDIM,
                                                lng + (size_t)i*FDIM, lnb + (size_t)i*FDIM,
                                                (i == 0) ? 1 : 0);
    }

    // pool + head
    pool<<<BSZ, FDIM>>>(xp, poolp);
    gemm_out<<<BSZ/8, 128>>>(poolp, outW, outb, op);
    ln_gelu<<<(BSZ*32 + 255)/256, 256>>>(op, out, (__nv_bfloat16*)nullptr, (__nv_bfloat16*)nullptr,
                                         olng, olnb, BSZ, OUTD, 1);
}

// round 6
// speedup vs baseline: 2.5081x; 1.2423x over previous
#include <cuda_runtime.h>
#include <cuda_bf16.h>
#include <math.h>
#include <stdint.h>

// ---------------- problem constants ----------------
#define BSZ    1024
#define NNODE  80
#define LMIR   30
#define NDIM   256
#define FDIM   512
#define HEADS  4
#define CDIM   128
#define OUTD   128
#define MROWS  (BSZ*NNODE)       // 81920
#define LN_EPS 1e-5f

// int8 GEMM tiling: CTA 128x128, 8 warps (2 M x 4 N), warp tile 64x32, stage K=64
#define BM 128
#define BN 128
#define KSTG 64
#define NSTG 3
#define STG_BYTES 32768                 // Aq1 8K + Aq2 8K + Bq1 8K + Bq2 8K
#define GEMM_SMEM (NSTG*STG_BYTES)      // 96KB

// ---------------- device scratch ----------------
__device__ int8_t g_aq1 [(size_t)MROWS*FDIM];
__device__ int8_t g_aq2 [(size_t)MROWS*FDIM];
__device__ float  g_as  [(size_t)MROWS];
__device__ int8_t g_wiq1[(size_t)FDIM*NDIM];       // in_W^T quant [N=512,K=256]
__device__ int8_t g_wiq2[(size_t)FDIM*NDIM];
__device__ float  g_wis [(size_t)FDIM];
__device__ int8_t g_wcq1[(size_t)2*1024*FDIM];     // concat(Wl,Wr)^T per layer [N=1024,K=512]
__device__ int8_t g_wcq2[(size_t)2*1024*FDIM];
__device__ float  g_wcs [(size_t)2*1024];
__device__ float  g_bcat[(size_t)2*1024];
__device__ float  g_x   [(size_t)MROWS*FDIM];
__device__ float  g_xlr [(size_t)MROWS*1024];      // [xl | xr]
__device__ float  g_h   [(size_t)MROWS*FDIM];
__device__ float  g_pool[(size_t)BSZ*2*FDIM];
__device__ float  g_o   [(size_t)BSZ*OUTD];

// ---------------- PTX helpers ----------------
__device__ __forceinline__ uint32_t smem_u32(const void* p) {
    uint32_t a;
    asm("{ .reg .u64 t; cvta.to.shared.u64 t, %1; cvt.u32.u64 %0, t; }" : "=r"(a) : "l"(p));
    return a;
}
__device__ __forceinline__ void cp16(uint32_t saddr, const void* gaddr) {
    asm volatile("cp.async.cg.shared.global [%0], [%1], 16;" :: "r"(saddr), "l"(gaddr));
}
#define CP_COMMIT() asm volatile("cp.async.commit_group;" ::: "memory")

// swizzle for 64B rows: chunk(bits 4-5) ^= row bits 1-2 (bits 7-8)
__device__ __forceinline__ uint32_t swz64(uint32_t off) { return off ^ ((off >> 3) & 0x30); }

#define LDMX4(r0,r1,r2,r3,a) \
    asm volatile("ldmatrix.sync.aligned.m8n8.x4.shared.b16 {%0,%1,%2,%3}, [%4];" \
        : "=r"(r0), "=r"(r1), "=r"(r2), "=r"(r3) : "r"(a))

#define IMMA(c, a, b0, b1) \
    asm volatile("mma.sync.aligned.m16n8k32.row.col.s32.s8.s8.s32 " \
        "{%0,%1,%2,%3}, {%4,%5,%6,%7}, {%8,%9}, {%0,%1,%2,%3};" \
        : "+r"((c)[0]), "+r"((c)[1]), "+r"((c)[2]), "+r"((c)[3]) \
        : "r"((a)[0]), "r"((a)[1]), "r"((a)[2]), "r"((a)[3]), "r"(b0), "r"(b1))

// ---------------- quantization helpers ----------------
// x ~= s*(q1 + q2/254), s = rowmax/127, q1,q2 in [-127,127]
__device__ __forceinline__ void quant2(float v, float inv127, int& q1, int& q2) {
    float a = v * inv127;            // = v*127/m
    float f1 = rintf(a);
    q1 = (int)f1;
    q2 = (int)rintf((a - f1) * 254.f);
}
__device__ __forceinline__ uint32_t pack4(int a, int b, int c, int d) {
    return (uint32_t)(a & 255) | ((uint32_t)(b & 255) << 8) |
           ((uint32_t)(c & 255) << 16) | ((uint32_t)(d & 255) << 24);
}
__device__ __forceinline__ float warp_max(float m) {
    #pragma unroll
    for (int o = 16; o; o >>= 1) m = fmaxf(m, __shfl_xor_sync(0xffffffffu, m, o));
    return m;
}

// ---------------- weight prep: per-column quantize (warp per column) ----------------
__global__ void prep_weights(const float* __restrict__ in_W,
                             const float* __restrict__ Wl, const float* __restrict__ Wr,
                             const float* __restrict__ bl, const float* __restrict__ br) {
    int gw = (blockIdx.x * blockDim.x + threadIdx.x) >> 5;
    int lane = threadIdx.x & 31;
    if (gw < FDIM) {
        // input W column n: K=256, lane holds 8 values
        int n = gw;
        float v[8];
        float m = 0.f;
        #pragma unroll
        for (int j = 0; j < 8; j++) {
            v[j] = in_W[(size_t)(lane*8 + j) * FDIM + n];
            m = fmaxf(m, fabsf(v[j]));
        }
        m = fmaxf(warp_max(m), 1e-20f);
        if (lane == 0) g_wis[n] = m * (1.f/127.f);
        float inv = 127.f / m;
        int q1[8], q2[8];
        #pragma unroll
        for (int j = 0; j < 8; j++) quant2(v[j], inv, q1[j], q2[j]);
        uint2 p1 = make_uint2(pack4(q1[0],q1[1],q1[2],q1[3]), pack4(q1[4],q1[5],q1[6],q1[7]));
        uint2 p2 = make_uint2(pack4(q2[0],q2[1],q2[2],q2[3]), pack4(q2[4],q2[5],q2[6],q2[7]));
        *(uint2*)(g_wiq1 + (size_t)n*NDIM + lane*8) = p1;
        *(uint2*)(g_wiq2 + (size_t)n*NDIM + lane*8) = p2;
        return;
    }
    int w2 = gw - FDIM;
    if (w2 < 2*1024) {
        int i = w2 >> 10, n = w2 & 1023;          // layer i, output col n of [Wl|Wr]
        float v[16];
        float m = 0.f;
        #pragma unroll
        for (int j = 0; j < 16; j++) {
            int k = lane*16 + j;
            float val = (n < FDIM) ? Wl[(size_t)i*FDIM*FDIM + (size_t)k*FDIM + n]
                                   : Wr[(size_t)i*FDIM*FDIM + (size_t)k*FDIM + (n - FDIM)];
            v[j] = val;
            m = fmaxf(m, fabsf(val));
        }
        m = fmaxf(warp_max(m), 1e-20f);
        if (lane == 0) {
            g_wcs[i*1024 + n] = m * (1.f/127.f);
            g_bcat[i*1024 + n] = (n < FDIM) ? bl[i*FDIM + n] : br[i*FDIM + (n - FDIM)];
        }
        float inv = 127.f / m;
        int q1[16], q2[16];
        #pragma unroll
        for (int j = 0; j < 16; j++) quant2(v[j], inv, q1[j], q2[j]);
        uint4 p1 = make_uint4(pack4(q1[0],q1[1],q1[2],q1[3]),   pack4(q1[4],q1[5],q1[6],q1[7]),
                              pack4(q1[8],q1[9],q1[10],q1[11]), pack4(q1[12],q1[13],q1[14],q1[15]));
        uint4 p2 = make_uint4(pack4(q2[0],q2[1],q2[2],q2[3]),   pack4(q2[4],q2[5],q2[6],q2[7]),
                              pack4(q2[8],q2[9],q2[10],q2[11]), pack4(q2[12],q2[13],q2[14],q2[15]));
        size_t off = (size_t)(i*1024 + n) * FDIM + lane*16;
        *(uint4*)(g_wcq1 + off) = p1;
        *(uint4*)(g_wcq2 + off) = p2;
    }
}

// ---------------- build x0: concat + node emb, quantize rows (warp per row) ----------------
__global__ void build_x0(const float* __restrict__ mirna,
                         const float* __restrict__ target,
                         const float* __restrict__ ntype) {
    int row = (blockIdx.x * blockDim.x + threadIdx.x) >> 5;
    if (row >= MROWS) return;
    int lane = threadIdx.x & 31;
    int b = row / NNODE, v = row % NNODE;
    const float* src; const float* emb;
    if (v < LMIR) { src = mirna  + ((size_t)b*LMIR + v) * NDIM;                emb = ntype; }
    else          { src = target + ((size_t)b*(NNODE-LMIR) + (v-LMIR)) * NDIM; emb = ntype + NDIM; }
    float vals[8];
    float m = 0.f;
    #pragma unroll
    for (int h = 0; h < 2; h++) {
        float4 a = *(const float4*)(src + lane*8 + h*4);
        float4 e = *(const float4*)(emb + lane*8 + h*4);
        vals[h*4+0] = a.x+e.x; vals[h*4+1] = a.y+e.y; vals[h*4+2] = a.z+e.z; vals[h*4+3] = a.w+e.w;
    }
    #pragma unroll
    for (int j = 0; j < 8; j++) m = fmaxf(m, fabsf(vals[j]));
    m = fmaxf(warp_max(m), 1e-20f);
    if (lane == 0) g_as[row] = m * (1.f/127.f);
    float inv = 127.f / m;
    int q1[8], q2[8];
    #pragma unroll
    for (int j = 0; j < 8; j++) quant2(vals[j], inv, q1[j], q2[j]);
    *(uint2*)(g_aq1 + (size_t)row*NDIM + lane*8) =
        make_uint2(pack4(q1[0],q1[1],q1[2],q1[3]), pack4(q1[4],q1[5],q1[6],q1[7]));
    *(uint2*)(g_aq2 + (size_t)row*NDIM + lane*8) =
        make_uint2(pack4(q2[0],q2[1],q2[2],q2[3]), pack4(q2[4],q2[5],q2[6],q2[7]));
}

// ---------------- int8 split GEMM: C = A@B^T + bias ----------------
// A: q1/q2 [M,K] s8, row scale sa; B: q1/q2 [N,K] s8, col scale sb.
// C fp32 [M,N]. grid (N/128, M/128), 256 threads.
__global__ __launch_bounds__(256, 1) void gemm_i8(
    const int8_t* __restrict__ Aq1, const int8_t* __restrict__ Aq2, const float* __restrict__ sa,
    const int8_t* __restrict__ Bq1, const int8_t* __restrict__ Bq2, const float* __restrict__ sb,
    const float* __restrict__ bias, float* __restrict__ C, int K, int N)
{
    extern __shared__ char sm[];
    const uint32_t smem_base = smem_u32(sm);
    const int tid = threadIdx.x;
    const int wid = tid >> 5, lane = tid & 31;
    const int m0 = blockIdx.y * BM;
    const int n0 = blockIdx.x * BN;
    const int nchunk = K >> 6;
    const int warpM = (wid & 1) * 64;
    const int warpN = (wid >> 1) * 32;
    const int quad = lane >> 3, qr = lane & 7;

    int acc1[4][4][4], acc2[4][4][4];
    #pragma unroll
    for (int i = 0; i < 4; i++)
        #pragma unroll
        for (int j = 0; j < 4; j++)
            #pragma unroll
            for (int q = 0; q < 4; q++) { acc1[i][j][q] = 0; acc2[i][j][q] = 0; }

    const int8_t* bases[4] = { Aq1 + (size_t)m0 * K, Aq2 + (size_t)m0 * K,
                               Bq1 + (size_t)n0 * K, Bq2 + (size_t)n0 * K };

    auto load_stage = [&](int slot, int c) {
        const uint32_t sb_ = smem_base + slot * STG_BYTES;
        const int k0 = c * KSTG;
        #pragma unroll
        for (int i = 0; i < 8; i++) {
            int idx = tid + i * 256;              // 0..2047
            int sub = idx >> 9, w = idx & 511;
            int row = w >> 2, ch = w & 3;
            cp16(sb_ + (sub << 13) + swz64((row << 6) + (ch << 4)),
                 bases[sub] + (size_t)row * K + k0 + ch * 16);
        }
        CP_COMMIT();
    };

    load_stage(0, 0);
    load_stage(1, 1);

    for (int c = 0; c < nchunk; ++c) {
        if (c < nchunk - 1) asm volatile("cp.async.wait_group 1;" ::: "memory");
        else                asm volatile("cp.async.wait_group 0;" ::: "memory");
        __syncthreads();
        if (c + 2 < nchunk) load_stage((c + 2) % NSTG, c + 2);

        const uint32_t sb_ = smem_base + (c % NSTG) * STG_BYTES;
        #pragma unroll
        for (int kc = 0; kc < 2; ++kc) {          // two k32 steps per stage
            const int kb = kc*32 + (quad >> 1) * 16;
            // B fragments: two LDMX4 per tensor covering n32
            uint32_t bq1f[2][4], bq2f[2][4];
            #pragma unroll
            for (int g = 0; g < 2; ++g) {
                int nrow = warpN + g*16 + (quad & 1)*8 + qr;
                uint32_t off = swz64((nrow << 6) + kb);
                LDMX4(bq1f[g][0], bq1f[g][1], bq1f[g][2], bq1f[g][3], sb_ + 16384 + off);
                LDMX4(bq2f[g][0], bq2f[g][1], bq2f[g][2], bq2f[g][3], sb_ + 24576 + off);
            }
            #pragma unroll
            for (int mt = 0; mt < 4; ++mt) {
                int arow = warpM + mt*16 + (quad & 1)*8 + qr;
                uint32_t off = swz64((arow << 6) + kb);
                uint32_t aq1f[4], aq2f[4];
                LDMX4(aq1f[0], aq1f[1], aq1f[2], aq1f[3], sb_ + off);
                LDMX4(aq2f[0], aq2f[1], aq2f[2], aq2f[3], sb_ + 8192 + off);
                #pragma unroll
                for (int ng = 0; ng < 4; ++ng) {
                    uint32_t b0 = bq1f[ng>>1][ng&1], b1 = bq1f[ng>>1][2+(ng&1)];
                    uint32_t c0 = bq2f[ng>>1][ng&1], c1 = bq2f[ng>>1][2+(ng&1)];
                    IMMA(acc1[mt][ng], aq1f, b0, b1);
                    IMMA(acc2[mt][ng], aq1f, c0, c1);
                    IMMA(acc2[mt][ng], aq2f, b0, b1);
                }
            }
        }
    }

    // epilogue: C = sa*sb*(S1 + S2/254) + bias
    const float INV254 = 1.f/254.f;
    const int r = lane >> 2, c2 = (lane & 3) * 2;
    #pragma unroll
    for (int mt = 0; mt < 4; ++mt) {
        int row0 = m0 + warpM + mt*16 + r;
        float sa0 = sa[row0], sa1 = sa[row0 + 8];
        #pragma unroll
        for (int ng = 0; ng < 4; ++ng) {
            int col = n0 + warpN + ng*8 + c2;
            float sb0 = sb[col], sb1 = sb[col+1];
            float bx = bias[col], by = bias[col+1];
            float2 v0, v1;
            v0.x = sa0*sb0*((float)acc1[mt][ng][0] + (float)acc2[mt][ng][0]*INV254) + bx;
            v0.y = sa0*sb1*((float)acc1[mt][ng][1] + (float)acc2[mt][ng][1]*INV254) + by;
            v1.x = sa1*sb0*((float)acc1[mt][ng][2] + (float)acc2[mt][ng][2]*INV254) + bx;
            v1.y = sa1*sb1*((float)acc1[mt][ng][3] + (float)acc2[mt][ng][3]*INV254) + by;
            *(float2*)&C[(size_t)row0 * N + col]       = v0;
            *(float2*)&C[(size_t)(row0 + 8) * N + col] = v1;
        }
    }
}

// ---------------- warp-per-row LayerNorm + GELU (+ optional int8 quant out) ----------------
__global__ void ln_gelu(const float* __restrict__ in, float* __restrict__ out,
                        int8_t* q1p, int8_t* q2p, float* sap,
                        const float* __restrict__ g, const float* __restrict__ b,
                        int rows, int width, int dogelu)
{
    int row = (blockIdx.x * blockDim.x + threadIdx.x) >> 5;
    if (row >= rows) return;
    int lane = threadIdx.x & 31;
    const float* rp = in + (size_t)row * width;
    int nv = width >> 7;
    float vals[16];
    float s = 0.f, ss = 0.f;
    for (int i = 0; i < nv; i++) {
        float4 v = *(const float4*)(rp + lane*4 + i*128);
        vals[i*4+0]=v.x; vals[i*4+1]=v.y; vals[i*4+2]=v.z; vals[i*4+3]=v.w;
        s  += v.x + v.y + v.z + v.w;
        ss += v.x*v.x + v.y*v.y + v.z*v.z + v.w*v.w;
    }
    #pragma unroll
    for (int o = 16; o; o >>= 1) {
        s  += __shfl_xor_sync(0xffffffffu, s,  o);
        ss += __shfl_xor_sync(0xffffffffu, ss, o);
    }
    float inv_w = 1.f / (float)width;
    float mu = s * inv_w;
    float var = ss * inv_w - mu * mu;
    float rr = rsqrtf(var + LN_EPS);
    float* op = out + (size_t)row * width;
    float m = 0.f;
    for (int i = 0; i < nv; i++) {
        int f = lane*4 + i*128;
        float4 gg = *(const float4*)(g + f);
        float4 bb = *(const float4*)(b + f);
        float y0 = (vals[i*4+0]-mu)*rr*gg.x + bb.x;
        float y1 = (vals[i*4+1]-mu)*rr*gg.y + bb.y;
        float y2 = (vals[i*4+2]-mu)*rr*gg.z + bb.z;
        float y3 = (vals[i*4+3]-mu)*rr*gg.w + bb.w;
        if (dogelu) {
            y0 = 0.5f*y0*(1.f+erff(y0*0.70710678118654752f));
            y1 = 0.5f*y1*(1.f+erff(y1*0.70710678118654752f));
            y2 = 0.5f*y2*(1.f+erff(y2*0.70710678118654752f));
            y3 = 0.5f*y3*(1.f+erff(y3*0.70710678118654752f));
        }
        vals[i*4+0]=y0; vals[i*4+1]=y1; vals[i*4+2]=y2; vals[i*4+3]=y3;
        m = fmaxf(fmaxf(fmaxf(fabsf(y0), fabsf(y1)), fmaxf(fabsf(y2), fabsf(y3))), m);
        *(float4*)(op + f) = make_float4(y0, y1, y2, y3);
    }
    if (q1p) {
        m = fmaxf(warp_max(m), 1e-20f);
        if (lane == 0) sap[row] = m * (1.f/127.f);
        float inv = 127.f / m;
        for (int i = 0; i < nv; i++) {
            int q1[4], q2[4];
            #pragma unroll
            for (int j = 0; j < 4; j++) quant2(vals[i*4+j], inv, q1[j], q2[j]);
            uint32_t* d1 = (uint32_t*)(q1p + (size_t)row*width) + i*32 + lane;
            uint32_t* d2 = (uint32_t*)(q2p + (size_t)row*width) + i*32 + lane;
            *d1 = pack4(q1[0],q1[1],q1[2],q1[3]);
            *d2 = pack4(q2[0],q2[1],q2[2],q2[3]);
        }
    }
}

// ---------------- residual + LN (+ optional GELU, + optional quant out) ----------------
__global__ void resid_ln(const float* __restrict__ h, float* __restrict__ x,
                         int8_t* q1p, int8_t* q2p, float* sap,
                         const float* __restrict__ bo, const float* __restrict__ g,
                         const float* __restrict__ b, int dogelu)
{
    int row = (blockIdx.x * blockDim.x + threadIdx.x) >> 5;
    if (row >= MROWS) return;
    int lane = threadIdx.x & 31;
    const float* hp = h + (size_t)row * FDIM;
    float* xp = x + (size_t)row * FDIM;
    float vals[16];
    float s = 0.f, ss = 0.f;
    #pragma unroll
    for (int i = 0; i < 4; i++) {
        int f = lane*4 + i*128;
        float4 hv = *(const float4*)(hp + f);
        float4 xv = *(const float4*)(xp + f);
        float4 bv = *(const float4*)(bo + f);
        float v0 = hv.x + bv.x + xv.x;
        float v1 = hv.y + bv.y + xv.y;
        float v2 = hv.z + bv.z + xv.z;
        float v3 = hv.w + bv.w + xv.w;
        vals[i*4+0]=v0; vals[i*4+1]=v1; vals[i*4+2]=v2; vals[i*4+3]=v3;
        s  += v0+v1+v2+v3;
        ss += v0*v0+v1*v1+v2*v2+v3*v3;
    }
    #pragma unroll
    for (int o = 16; o; o >>= 1) {
        s  += __shfl_xor_sync(0xffffffffu, s,  o);
        ss += __shfl_xor_sync(0xffffffffu, ss, o);
    }
    float mu = s * (1.f/FDIM);
    float var = ss * (1.f/FDIM) - mu*mu;
    float rr = rsqrtf(var + LN_EPS);
    float m = 0.f;
    #pragma unroll
    for (int i = 0; i < 4; i++) {
        int f = lane*4 + i*128;
        float4 gg = *(const float4*)(g + f);
        float4 bb = *(const float4*)(b + f);
        float y0 = (vals[i*4+0]-mu)*rr*gg.x + bb.x;
        float y1 = (vals[i*4+1]-mu)*rr*gg.y + bb.y;
        float y2 = (vals[i*4+2]-mu)*rr*gg.z + bb.z;
        float y3 = (vals[i*4+3]-mu)*rr*gg.w + bb.w;
        if (dogelu) {
            y0 = 0.5f*y0*(1.f+erff(y0*0.70710678118654752f));
            y1 = 0.5f*y1*(1.f+erff(y1*0.70710678118654752f));
            y2 = 0.5f*y2*(1.f+erff(y2*0.70710678118654752f));
            y3 = 0.5f*y3*(1.f+erff(y3*0.70710678118654752f));
        }
        vals[i*4+0]=y0; vals[i*4+1]=y1; vals[i*4+2]=y2; vals[i*4+3]=y3;
        m = fmaxf(fmaxf(fmaxf(fabsf(y0), fabsf(y1)), fmaxf(fabsf(y2), fabsf(y3))), m);
        *(float4*)(xp + f) = make_float4(y0, y1, y2, y3);
    }
    if (q1p) {
        m = fmaxf(warp_max(m), 1e-20f);
        if (lane == 0) sap[row] = m * (1.f/127.f);
        float inv = 127.f / m;
        #pragma unroll
        for (int i = 0; i < 4; i++) {
            int q1[4], q2[4];
            #pragma unroll
            for (int j = 0; j < 4; j++) quant2(vals[i*4+j], inv, q1[j], q2[j]);
            uint32_t* d1 = (uint32_t*)(q1p + (size_t)row*FDIM) + i*32 + lane;
            uint32_t* d2 = (uint32_t*)(q2p + (size_t)row*FDIM) + i*32 + lane;
            *d1 = pack4(q1[0],q1[1],q1[2],q1[3]);
            *d2 = pack4(q2[0],q2[1],q2[2],q2[3]);
        }
    }
}

// ---------------- GAT aggregation (xl/xr packed as [M,1024] = [xl|xr]) ----------------
__global__ __launch_bounds__(256) void gat(
    const float* __restrict__ xlr,
    const float* __restrict__ etype_emb,   // [3,4]
    const float* __restrict__ We,          // [4,512]
    const float* __restrict__ att,         // [4,128]
    float* __restrict__ hout)
{
    extern __shared__ char sm[];
    float* xls = (float*)sm;               // 80*512
    float* ee0 = xls + NNODE*FDIM;
    float* ee2 = ee0 + FDIM;
    const int b = blockIdx.x;
    const int tid = threadIdx.x;

    for (int f = tid; f < FDIM; f += 256) {
        float s0 = 0.f, s2 = 0.f;
        #pragma unroll
        for (int j = 0; j < 4; j++) {
            float w = We[j*FDIM + f];
            s0 += etype_emb[j]     * w;
            s2 += etype_emb[8 + j] * w;
        }
        ee0[f] = s0; ee2[f] = s2;
    }
    const float* xlb = xlr + (size_t)b * NNODE * 1024;
    for (int i4 = tid; i4 < NNODE*FDIM/4; i4 += 256) {
        int row = i4 >> 7, c4 = (i4 & 127) << 2;
        *(float4*)(xls + row*FDIM + c4) = *(const float4*)(xlb + (size_t)row*1024 + c4);
    }
    __syncthreads();

    const int lane = tid & 31, wid = tid >> 5;
    for (int t = wid; t < NNODE*HEADS; t += 8) {
        const int v = t >> 2, h = t & 3;
        const int base = h*CDIM + lane;
        const float* xrp = xlr + ((size_t)b*NNODE + v)*1024 + FDIM + base;
        float xrr[4], atr[4];
        #pragma unroll
        for (int j = 0; j < 4; j++) {
            xrr[j] = xrp[32*j];
            atr[j] = att[h*CDIM + lane + 32*j];
        }
        const int lo = (v < LMIR) ? 0 : LMIR;
        const int hi = (v < LMIR) ? (LMIR-1) : (NNODE-1);
        int   srcs[5];
        float c0[5], c2[5], valid[5];
        srcs[0]=v-1; srcs[1]=v+1; srcs[2]=v-2; srcs[3]=v+2; srcs[4]=v;
        valid[0] = (v-1 >= lo) ? 1.f : 0.f;
        valid[1] = (v+1 <= hi) ? 1.f : 0.f;
        valid[2] = (v-2 >= lo) ? 1.f : 0.f;
        valid[3] = (v+2 <= hi) ? 1.f : 0.f;
        valid[4] = 1.f;
        c0[0]=1.f; c2[0]=0.f;  c0[1]=1.f; c2[1]=0.f;
        c0[2]=0.f; c2[2]=1.f;  c0[3]=0.f; c2[3]=1.f;
        float n0 = valid[0] + valid[1];
        float n2 = valid[2] + valid[3];
        float inv = 1.f / (n0 + n2);
        c0[4] = n0 * inv; c2[4] = n2 * inv;
        #pragma unroll
        for (int e = 0; e < 5; e++) {
            int s = srcs[e];
            s = s < 0 ? 0 : (s > NNODE-1 ? NNODE-1 : s);
            srcs[e] = s;
        }
        float a[5];
        #pragma unroll
        for (int e = 0; e < 5; e++) {
            const float* xp = xls + srcs[e]*FDIM + base;
            float p = 0.f;
            #pragma unroll
            for (int j = 0; j < 4; j++) {
                int off = 32*j;
                float mm = xp[off] + xrr[j] + c0[e]*ee0[base+off] + c2[e]*ee2[base+off];
                mm = (mm > 0.f) ? mm : 0.2f*mm;
                p += mm * atr[j];
            }
            #pragma unroll
            for (int o = 16; o; o >>= 1) p += __shfl_xor_sync(0xffffffffu, p, o);
            a[e] = (valid[e] > 0.f) ? p : -1e30f;
        }
        float amax = a[0];
        #pragma unroll
        for (int e = 1; e < 5; e++) amax = fmaxf(amax, a[e]);
        float den = 0.f;
        #pragma unroll
        for (int e = 0; e < 5; e++) { a[e] = expf(a[e] - amax); den += a[e]; }
        float invd = 1.f / den;
        float o0=0.f, o1=0.f, o2=0.f, o3=0.f;
        #pragma unroll
        for (int e = 0; e < 5; e++) {
            float al = a[e] * invd;
            const float* xp = xls + srcs[e]*FDIM + base;
            o0 += al * xp[0];
            o1 += al * xp[32];
            o2 += al * xp[64];
            o3 += al * xp[96];
        }
        float* op = hout + ((size_t)b*NNODE + v)*FDIM + base;
        op[0]=o0; op[32]=o1; op[64]=o2; op[96]=o3;
    }
}

// ---------------- mean/max pool ----------------
__global__ void pool(const float* __restrict__ x, float* __restrict__ pooled) {
    int b = blockIdx.x;
    int f = threadIdx.x;
    const float* xp = x + (size_t)b * NNODE * FDIM + f;
    float s = 0.f, mx = -3.4e38f;
    #pragma unroll 4
    for (int v = 0; v < NNODE; v++) {
        float val = xp[(size_t)v * FDIM];
        s += val;
        mx = fmaxf(mx, val);
    }
    pooled[(size_t)b*2*FDIM + f]        = s * (1.f/NNODE);
    pooled[(size_t)b*2*FDIM + FDIM + f] = mx;
}

// ---------------- head GEMM (tiny, fp32) ----------------
__global__ __launch_bounds__(128) void gemm_out(
    const float* __restrict__ A, const float* __restrict__ Bw,
    const float* __restrict__ bias, float* __restrict__ C)
{
    __shared__ float As[8][1024];
    const int r0 = blockIdx.x * 8;
    const int tid = threadIdx.x;
    for (int i4 = tid; i4 < 8*1024/4; i4 += 128)
        *(float4*)(&As[0][0] + (size_t)i4*4) = *(const float4*)(A + (size_t)r0*1024 + (size_t)i4*4);
    __syncthreads();
    float acc[8];
    #pragma unroll
    for (int r = 0; r < 8; r++) acc[r] = 0.f;
    #pragma unroll 4
    for (int k = 0; k < 1024; k++) {
        float bv = Bw[(size_t)k*128 + tid];
        #pragma unroll
        for (int r = 0; r < 8; r++) acc[r] += As[r][k] * bv;
    }
    float bi = bias[tid];
    #pragma unroll
    for (int r = 0; r < 8; r++)
        C[(size_t)(r0 + r)*128 + tid] = acc[r] + bi;
}

// ---------------- launch ----------------
extern "C" void kernel_launch(void* const* d_in, const int* in_sizes, int n_in,
                              void* d_out, int out_size) {
    const float* mirna  = (const float*)d_in[0];
    const float* target = (const float*)d_in[1];
    const float* ntype  = (const float*)d_in[2];
    const float* etype  = (const float*)d_in[3];
    const float* in_W   = (const float*)d_in[4];
    const float* in_b   = (const float*)d_in[5];
    const float* in_lng = (const float*)d_in[6];
    const float* in_lnb = (const float*)d_in[7];
    const float* Wl     = (const float*)d_in[8];
    const float* bl     = (const float*)d_in[9];
    const float* Wr     = (const float*)d_in[10];
    const float* br     = (const float*)d_in[11];
    const float* We     = (const float*)d_in[12];
    const float* attw   = (const float*)d_in[13];
    const float* bo     = (const float*)d_in[14];
    const float* lng    = (const float*)d_in[15];
    const float* lnb    = (const float*)d_in[16];
    const float* outW   = (const float*)d_in[17];
    const float* outb   = (const float*)d_in[18];
    const float* olng   = (const float*)d_in[19];
    const float* olnb   = (const float*)d_in[20];
    float* out = (float*)d_out;

    float *xp, *xlrp, *hp, *poolp, *op, *bcatp, *asp, *wisp, *wcsp;
    int8_t *aq1p, *aq2p, *wiq1p, *wiq2p, *wcq1p, *wcq2p;
    cudaGetSymbolAddress((void**)&aq1p,  g_aq1);
    cudaGetSymbolAddress((void**)&aq2p,  g_aq2);
    cudaGetSymbolAddress((void**)&asp,   g_as);
    cudaGetSymbolAddress((void**)&wiq1p, g_wiq1);
    cudaGetSymbolAddress((void**)&wiq2p, g_wiq2);
    cudaGetSymbolAddress((void**)&wisp,  g_wis);
    cudaGetSymbolAddress((void**)&wcq1p, g_wcq1);
    cudaGetSymbolAddress((void**)&wcq2p, g_wcq2);
    cudaGetSymbolAddress((void**)&wcsp,  g_wcs);
    cudaGetSymbolAddress((void**)&bcatp, g_bcat);
    cudaGetSymbolAddress((void**)&xp,    g_x);
    cudaGetSymbolAddress((void**)&xlrp,  g_xlr);
    cudaGetSymbolAddress((void**)&hp,    g_h);
    cudaGetSymbolAddress((void**)&poolp, g_pool);
    cudaGetSymbolAddress((void**)&op,    g_o);

    const int GAT_SMEM = (NNODE*FDIM + 2*FDIM) * sizeof(float);
    cudaFuncSetAttribute(gat, cudaFuncAttributeMaxDynamicSharedMemorySize, GAT_SMEM);
    cudaFuncSetAttribute(gemm_i8, cudaFuncAttributeMaxDynamicSharedMemorySize, GEMM_SMEM);

    // weight quantization (warp per output column): 512 + 2048 warps
    prep_weights<<<(2560*32 + 255)/256, 256>>>(in_W, Wl, Wr, bl, br);
    // x0 build + quantize (warp per row)
    build_x0<<<(MROWS*32 + 255)/256, 256>>>(mirna, target, ntype);

    // input projection (M=81920, N=512, K=256)
    gemm_i8<<<dim3(FDIM/BN, MROWS/BM), 256, GEMM_SMEM>>>(
        aq1p, aq2p, asp, wiq1p, wiq2p, wisp, in_b, hp, NDIM, FDIM);
    ln_gelu<<<(MROWS*32 + 255)/256, 256>>>(hp, xp, aq1p, aq2p, asp,
                                           in_lng, in_lnb, MROWS, FDIM, 1);

    // GAT layers: fused [Wl|Wr] int8 GEMM (M=81920, N=1024, K=512)
    for (int i = 0; i < 2; i++) {
        gemm_i8<<<dim3(1024/BN, MROWS/BM), 256, GEMM_SMEM>>>(
            aq1p, aq2p, asp,
            wcq1p + (size_t)i*1024*FDIM, wcq2p + (size_t)i*1024*FDIM, wcsp + (size_t)i*1024,
            bcatp + (size_t)i*1024, xlrp, FDIM, 1024);
        gat<<<BSZ, 256, GAT_SMEM>>>(xlrp, etype,
                                    We + (size_t)i*HEADS*FDIM,
                                    attw + (size_t)i*HEADS*CDIM, hp);
        resid_ln<<<(MROWS*32 + 255)/256, 256>>>(hp, xp,
                                                (i == 0) ? aq1p : (int8_t*)nullptr,
                                                (i == 0) ? aq2p : (int8_t*)nullptr, asp,
                                                bo + (size_t)i*FDIM,
                                                lng + (size_t)i*FDIM, lnb + (size_t)i*FDIM,
                                                (i == 0) ? 1 : 0);
    }

    // pool + head
    pool<<<BSZ, FDIM>>>(xp, poolp);
    gemm_out<<<BSZ/8, 128>>>(poolp, outW, outb, op);
    ln_gelu<<<(BSZ*32 + 255)/256, 256>>>(op, out, (int8_t*)nullptr, (int8_t*)nullptr, (float*)nullptr,
                                         olng, olnb, BSZ, OUTD, 1);
}